// round 7
// baseline (speedup 1.0000x reference)
#include <cuda_runtime.h>
#include <cuda_fp16.h>
#include <cstdint>

#define N_EDGES  2000000
#define NUM_SEGS 500000
#define HID      128
#define NRB      4
#define TILE_M   256
#define NTILES   ((N_EDGES + TILE_M - 1) / TILE_M)   /* 7813, last tile 128 rows */
#define NTHREADS 512
#define WSTRIDE  136                  /* halves per W row: 128 + 8 pad */
#define RMS_EPS  1.1920928955078125e-07f

/* SMEM layout (bytes) */
#define OFF_W     0
#define SZ_W      (NRB * HID * WSTRIDE * 2)          /* 139264 */
#define OFF_WINB  (OFF_W + SZ_W)                     /* float4[128] */
#define OFF_BRESH (OFF_WINB + HID * 16)              /* half2[4*64]  */
#define OFF_WOUT  (OFF_BRESH + NRB * 64 * 4)         /* float[128] */
#define OFF_XS    (OFF_WOUT + HID * 4)               /* float4[256] */
#define SMEM_BYTES (OFF_XS + TILE_M * 16)

__device__ float    g_logits[N_EDGES];
__device__ unsigned g_segmax[NUM_SEGS];
__device__ float    g_segsum[NUM_SEGS];

__device__ __forceinline__ unsigned enc_f(float f) {
    unsigned b = __float_as_uint(f);
    return (b & 0x80000000u) ? ~b : (b | 0x80000000u);
}
__device__ __forceinline__ float dec_f(unsigned k) {
    unsigned b = (k & 0x80000000u) ? (k & 0x7FFFFFFFu) : ~k;
    return __uint_as_float(b);
}
__device__ __forceinline__ uint32_t pack_h2(float lo, float hi) {
    __half2 h = __floats2half2_rn(lo, hi);
    return *reinterpret_cast<uint32_t*>(&h);
}
__device__ __forceinline__ float2 unpack_h2(uint32_t u) {
    return __half22float2(*reinterpret_cast<__half2*>(&u));
}
__device__ __forceinline__ uint32_t hadd2_u(uint32_t a, uint32_t b) {
    __half2 r = __hadd2(*reinterpret_cast<__half2*>(&a), *reinterpret_cast<__half2*>(&b));
    return *reinterpret_cast<uint32_t*>(&r);
}
__device__ __forceinline__ uint32_t hmax2z_u(uint32_t a) {
    __half2 z = __float2half2_rn(0.f);
    __half2 r = __hmax2(*reinterpret_cast<__half2*>(&a), z);
    return *reinterpret_cast<uint32_t*>(&r);
}
__device__ __forceinline__ uint32_t hfma2_u(uint32_t a, uint32_t b, uint32_t c) {
    __half2 r = __hfma2(*reinterpret_cast<__half2*>(&a),
                        *reinterpret_cast<__half2*>(&b),
                        *reinterpret_cast<__half2*>(&c));
    return *reinterpret_cast<uint32_t*>(&r);
}
__device__ __forceinline__ void ldsm_x4(uint32_t& r0, uint32_t& r1, uint32_t& r2, uint32_t& r3,
                                        uint32_t addr) {
    asm volatile("ldmatrix.sync.aligned.m8n8.x4.shared.b16 {%0,%1,%2,%3}, [%4];\n"
                 : "=r"(r0), "=r"(r1), "=r"(r2), "=r"(r3) : "r"(addr));
}
__device__ __forceinline__ void mma16816(float* d,
        uint32_t a0, uint32_t a1, uint32_t a2, uint32_t a3,
        uint32_t b0, uint32_t b1) {
    asm volatile("mma.sync.aligned.m16n8k16.row.col.f32.f16.f16.f32 "
                 "{%0,%1,%2,%3}, {%4,%5,%6,%7}, {%8,%9}, {%0,%1,%2,%3};\n"
                 : "+f"(d[0]), "+f"(d[1]), "+f"(d[2]), "+f"(d[3])
                 : "r"(a0), "r"(a1), "r"(a2), "r"(a3), "r"(b0), "r"(b1));
}

__global__ void __launch_bounds__(NTHREADS, 1)
mlp_kernel(const float* __restrict__ ef, const int* __restrict__ ids,
           const float* __restrict__ W_in, const float* __restrict__ b_in,
           const float* __restrict__ rms_w, const float* __restrict__ W_res,
           const float* __restrict__ b_res, const float* __restrict__ W_out,
           const float* __restrict__ b_out)
{
    extern __shared__ char smem[];
    __half*   Wh   = (__half*)(smem + OFF_W);
    float4*   winb = (float4*)(smem + OFF_WINB);
    uint32_t* brsh = (uint32_t*)(smem + OFF_BRESH);
    float*    wout = (float*)(smem + OFF_WOUT);
    float4*   xs   = (float4*)(smem + OFF_XS);

    const int tid = threadIdx.x;

    /* ---- stage weights once per CTA; fold rms_w (per-k) into W_res ---- */
    for (int idx = tid; idx < NRB * HID * HID; idx += NTHREADS) {
        int i   = idx >> 14;
        int rem = idx & 16383;
        int n   = rem >> 7;
        int k   = rem & 127;
        float w = W_res[idx] * rms_w[i * HID + k];
        Wh[(i * HID + n) * WSTRIDE + k] = __float2half(w);
    }
    for (int c = tid; c < HID; c += NTHREADS) {
        winb[c] = make_float4(W_in[c * 3], W_in[c * 3 + 1], W_in[c * 3 + 2], b_in[c]);
        wout[c] = W_out[c];
    }
    for (int idx = tid; idx < NRB * 64; idx += NTHREADS) {
        int i = idx >> 6, c2 = idx & 63;
        brsh[idx] = pack_h2(b_res[i * HID + 2 * c2], b_res[i * HID + 2 * c2 + 1]);
    }

    const float bout = b_out[0];
    const int warp = tid >> 5, lane = tid & 31;
    const int q = lane & 3, gid = lane >> 2;

    uint32_t wbase = (uint32_t)__cvta_generic_to_shared(Wh);
    /* ldmatrix.x4 rows: lanes 0-7: tile j k[0,8) | 8-15: j k[8,16) |
       16-23: j+1 k[0,8) | 24-31: j+1 k[8,16) */
    uint32_t laneB = wbase +
        ((((lane & 7) + ((lane >> 4) & 1) * 8) * WSTRIDE) + ((lane >> 3) & 1) * 8) * 2;

    /* prefetch first tile's input rows (1 row / thread, 512 >= TILE_M) */
    float3 xpre = make_float3(0.f, 0.f, 0.f);
    if (tid < TILE_M) {
        long r = (long)blockIdx.x * TILE_M + tid;
        if (r < N_EDGES) xpre = make_float3(ef[r * 3], ef[r * 3 + 1], ef[r * 3 + 2]);
    }

    for (int tile = blockIdx.x; tile < NTILES; tile += gridDim.x) {
        __syncthreads();
        if (tid < TILE_M) xs[tid] = make_float4(xpre.x, xpre.y, xpre.z, 0.f);
        __syncthreads();

        /* warp owns rows [warp*16, warp*16+16) */
        float4 xv0 = xs[warp * 16 + gid];
        float4 xv1 = xs[warp * 16 + gid + 8];

        /* prefetch next tile while this one computes */
        {
            int nt = tile + gridDim.x;
            xpre = make_float3(0.f, 0.f, 0.f);
            if (nt < NTILES && tid < TILE_M) {
                long r = (long)nt * TILE_M + tid;
                if (r < N_EDGES)
                    xpre = make_float3(ef[r * 3], ef[r * 3 + 1], ef[r * 3 + 2]);
            }
        }

        /* ---- residual stream, packed fp16 A-fragment layout ----
           hp[4*ks+0]=(row gid,  cols 16ks+2q,+1)  hp[4*ks+1]=(row gid+8, same)
           hp[4*ks+2]=(row gid,  cols 16ks+8+2q,+1) hp[4*ks+3]=(row gid+8, same) */
        uint32_t hp[32];
        float ssf0 = 0.f, ssf1 = 0.f;

        /* ---- input layer straight into packed layout (f32 math) ---- */
        #pragma unroll
        for (int j = 0; j < 16; j++) {
            float4 w0 = winb[j * 8 + q * 2];
            float4 w1 = winb[j * 8 + q * 2 + 1];
            int i0 = 4 * (j >> 1) + (j & 1) * 2;
            float n0 = w0.w + xv0.x * w0.x + xv0.y * w0.y + xv0.z * w0.z;
            float n1 = w1.w + xv0.x * w1.x + xv0.y * w1.y + xv0.z * w1.z;
            float n2 = w0.w + xv1.x * w0.x + xv1.y * w0.y + xv1.z * w0.z;
            float n3 = w1.w + xv1.x * w1.x + xv1.y * w1.y + xv1.z * w1.z;
            hp[i0]     = pack_h2(n0, n1);
            hp[i0 + 1] = pack_h2(n2, n3);
            ssf0 += n0 * n0 + n1 * n1;
            ssf1 += n2 * n2 + n3 * n3;
        }

        /* ---- 4 residual blocks ---- */
        #pragma unroll 1
        for (int blk = 0; blk < NRB; blk++) {
            float v0 = ssf0, v1 = ssf1;
            v0 += __shfl_xor_sync(0xffffffffu, v0, 1);
            v0 += __shfl_xor_sync(0xffffffffu, v0, 2);
            v1 += __shfl_xor_sync(0xffffffffu, v1, 1);
            v1 += __shfl_xor_sync(0xffffffffu, v1, 2);
            float sc0 = rsqrtf(v0 * (1.f / HID) + RMS_EPS);
            float sc1 = rsqrtf(v1 * (1.f / HID) + RMS_EPS);

            uint32_t lb = laneB + blk * (HID * WSTRIDE * 2);
            const uint32_t* bb2 = brsh + blk * 64;

            /* nh=0 relu results parked here; hp untouched until nh=1's MMAs done */
            uint32_t rl0[16];

            /* N processed in two 64-col halves to keep y small (reg budget) */
            #pragma unroll
            for (int nh = 0; nh < 2; nh++) {
                float y[8][4];
                #pragma unroll
                for (int j = 0; j < 8; j++)
                    y[j][0] = y[j][1] = y[j][2] = y[j][3] = 0.f;

                #pragma unroll
                for (int ks = 0; ks < 8; ks++) {
                    #pragma unroll
                    for (int jj = 0; jj < 8; jj += 2) {
                        int j = nh * 8 + jj;
                        uint32_t b0, b1, b2, b3;
                        ldsm_x4(b0, b1, b2, b3,
                                lb + (uint32_t)((j * 8 * WSTRIDE + ks * 16) * 2));
                        mma16816(y[jj],     hp[4*ks], hp[4*ks+1], hp[4*ks+2], hp[4*ks+3], b0, b1);
                        mma16816(y[jj + 1], hp[4*ks], hp[4*ks+1], hp[4*ks+2], hp[4*ks+3], b2, b3);
                    }
                }

                /* f16x2 epilogue for this half (deferred hp write for nh=0) */
                #pragma unroll
                for (int jj = 0; jj < 8; jj++) {
                    int j = nh * 8 + jj;
                    float2 bb = unpack_h2(bb2[j * 4 + q]);
                    float t0 = fmaf(y[jj][0], sc0, bb.x);
                    float t1 = fmaf(y[jj][1], sc0, bb.y);
                    float t2 = fmaf(y[jj][2], sc1, bb.x);
                    float t3 = fmaf(y[jj][3], sc1, bb.y);
                    uint32_t r01 = hmax2z_u(pack_h2(t0, t1));
                    uint32_t r23 = hmax2z_u(pack_h2(t2, t3));
                    if (nh == 0) {
                        rl0[jj * 2]     = r01;
                        rl0[jj * 2 + 1] = r23;
                    } else {
                        int i0 = 4 * (j >> 1) + (j & 1) * 2;
                        hp[i0]     = hadd2_u(hp[i0],     r01);
                        hp[i0 + 1] = hadd2_u(hp[i0 + 1], r23);
                    }
                }
            }

            /* apply deferred nh=0 updates */
            #pragma unroll
            for (int jj = 0; jj < 8; jj++) {
                int i0 = 4 * (jj >> 1) + (jj & 1) * 2;   /* j = jj for nh=0 */
                hp[i0]     = hadd2_u(hp[i0],     rl0[jj * 2]);
                hp[i0 + 1] = hadd2_u(hp[i0 + 1], rl0[jj * 2 + 1]);
            }

            /* sum-of-squares over the full updated residual (h2 accumulate) */
            uint32_t nss0 = 0u, nss1 = 0u;
            #pragma unroll
            for (int i = 0; i < 16; i++) {
                nss0 = hfma2_u(hp[2 * i],     hp[2 * i],     nss0);
                nss1 = hfma2_u(hp[2 * i + 1], hp[2 * i + 1], nss1);
            }
            float2 a = unpack_h2(nss0);
            float2 b = unpack_h2(nss1);
            ssf0 = a.x + a.y;
            ssf1 = b.x + b.y;
        }

        /* ---- output layer (f32) + fused segment-max ---- */
        {
            float a0 = 0.f, a1 = 0.f;
            const float2* w2 = (const float2*)wout;
            #pragma unroll
            for (int j = 0; j < 16; j++) {
                float2 w = w2[j * 4 + q];
                int i0 = 4 * (j >> 1) + (j & 1) * 2;
                float2 hA = unpack_h2(hp[i0]);
                float2 hB = unpack_h2(hp[i0 + 1]);
                a0 += hA.x * w.x + hA.y * w.y;
                a1 += hB.x * w.x + hB.y * w.y;
            }
            a0 += __shfl_xor_sync(0xffffffffu, a0, 1);
            a0 += __shfl_xor_sync(0xffffffffu, a0, 2);
            a1 += __shfl_xor_sync(0xffffffffu, a1, 1);
            a1 += __shfl_xor_sync(0xffffffffu, a1, 2);
            if (q == 0) {
                long r0 = (long)tile * TILE_M + warp * 16 + gid;
                long r1 = r0 + 8;
                float l0 = a0 + bout, l1 = a1 + bout;
                if (r0 < N_EDGES) {
                    g_logits[r0] = l0;
                    atomicMax(&g_segmax[ids[r0]], enc_f(l0));
                }
                if (r1 < N_EDGES) {
                    g_logits[r1] = l1;
                    atomicMax(&g_segmax[ids[r1]], enc_f(l1));
                }
            }
        }
    }
}

__global__ void init_kernel() {
    int i = blockIdx.x * blockDim.x + threadIdx.x;
    if (i < NUM_SEGS) { g_segmax[i] = 0u; g_segsum[i] = 0.f; }
}

__global__ void exp_kernel(const int* __restrict__ ids, float* __restrict__ out) {
    int i = blockIdx.x * blockDim.x + threadIdx.x;
    if (i < N_EDGES) {
        int s = ids[i];
        float m = dec_f(g_segmax[s]);
        float e = expf(g_logits[i] - m);
        out[i] = e;
        atomicAdd(&g_segsum[s], e);
    }
}

__global__ void norm_kernel(const int* __restrict__ ids, float* __restrict__ out) {
    int i = blockIdx.x * blockDim.x + threadIdx.x;
    if (i < N_EDGES) out[i] = out[i] / g_segsum[ids[i]];
}

extern "C" void kernel_launch(void* const* d_in, const int* in_sizes, int n_in,
                              void* d_out, int out_size)
{
    const float* ef    = (const float*)d_in[0];
    const int*   ids   = (const int*)d_in[1];
    const float* W_in  = (const float*)d_in[2];
    const float* b_in  = (const float*)d_in[3];
    const float* rms_w = (const float*)d_in[4];
    const float* W_res = (const float*)d_in[5];
    const float* b_res = (const float*)d_in[6];
    const float* W_out = (const float*)d_in[7];
    const float* b_out = (const float*)d_in[8];
    float* out = (float*)d_out;

    cudaFuncSetAttribute(mlp_kernel, cudaFuncAttributeMaxDynamicSharedMemorySize, SMEM_BYTES);

    int dev = 0, sms = 148;
    cudaGetDevice(&dev);
    cudaDeviceGetAttribute(&sms, cudaDevAttrMultiProcessorCount, dev);
    if (sms <= 0) sms = 148;

    init_kernel<<<(NUM_SEGS + 255) / 256, 256>>>();
    mlp_kernel<<<sms, NTHREADS, SMEM_BYTES>>>(ef, ids, W_in, b_in, rms_w,
                                              W_res, b_res, W_out, b_out);
    exp_kernel<<<(N_EDGES + 255) / 256, 256>>>(ids, out);
    norm_kernel<<<(N_EDGES + 255) / 256, 256>>>(ids, out);
}

// round 9
// speedup vs baseline: 1.6316x; 1.6316x over previous
#include <cuda_runtime.h>
#include <cuda_fp16.h>
#include <cstdint>

#define N_EDGES  2000000
#define NUM_SEGS 500000
#define HID      128
#define NRB      4
#define TILE_M   256
#define NTILES   ((N_EDGES + TILE_M - 1) / TILE_M)   /* 7813, last tile 128 rows */
#define NTHREADS 256
#define WSTRIDE  136                  /* halves per W row: 128 + 8 pad */
#define RMS_EPS  1.1920928955078125e-07f

/* SMEM layout (bytes) */
#define OFF_W     0
#define SZ_W      (NRB * HID * WSTRIDE * 2)          /* 139264 */
#define OFF_WINB  (OFF_W + SZ_W)                     /* float4[128] */
#define OFF_BRESH (OFF_WINB + HID * 16)              /* half2[4*64]  */
#define OFF_WOUT  (OFF_BRESH + NRB * 64 * 4)         /* float[128] */
#define OFF_XS    (OFF_WOUT + HID * 4)               /* float4[256] */
#define SMEM_BYTES (OFF_XS + TILE_M * 16)

__device__ float    g_logits[N_EDGES];
__device__ unsigned g_segmax[NUM_SEGS];
__device__ float    g_segsum[NUM_SEGS];

__device__ __forceinline__ unsigned enc_f(float f) {
    unsigned b = __float_as_uint(f);
    return (b & 0x80000000u) ? ~b : (b | 0x80000000u);
}
__device__ __forceinline__ float dec_f(unsigned k) {
    unsigned b = (k & 0x80000000u) ? (k & 0x7FFFFFFFu) : ~k;
    return __uint_as_float(b);
}
__device__ __forceinline__ uint32_t pack_h2(float lo, float hi) {
    __half2 h = __floats2half2_rn(lo, hi);
    return *reinterpret_cast<uint32_t*>(&h);
}
__device__ __forceinline__ float2 unpack_h2(uint32_t u) {
    return __half22float2(*reinterpret_cast<__half2*>(&u));
}
__device__ __forceinline__ uint32_t hadd2_u(uint32_t a, uint32_t b) {
    __half2 r = __hadd2(*reinterpret_cast<__half2*>(&a), *reinterpret_cast<__half2*>(&b));
    return *reinterpret_cast<uint32_t*>(&r);
}
__device__ __forceinline__ uint32_t hmax2z_u(uint32_t a) {
    __half2 z = __float2half2_rn(0.f);
    __half2 r = __hmax2(*reinterpret_cast<__half2*>(&a), z);
    return *reinterpret_cast<uint32_t*>(&r);
}
__device__ __forceinline__ uint32_t hfma2_u(uint32_t a, uint32_t b, uint32_t c) {
    __half2 r = __hfma2(*reinterpret_cast<__half2*>(&a),
                        *reinterpret_cast<__half2*>(&b),
                        *reinterpret_cast<__half2*>(&c));
    return *reinterpret_cast<uint32_t*>(&r);
}
__device__ __forceinline__ void ldsm_x4(uint32_t& r0, uint32_t& r1, uint32_t& r2, uint32_t& r3,
                                        uint32_t addr) {
    asm volatile("ldmatrix.sync.aligned.m8n8.x4.shared.b16 {%0,%1,%2,%3}, [%4];\n"
                 : "=r"(r0), "=r"(r1), "=r"(r2), "=r"(r3) : "r"(addr));
}
/* f16 accumulator variant: d = {d0,d1} half2 regs.
   d0 = (row gid, cols 8j+2q,+1), d1 = (row gid+8, same cols) */
__device__ __forceinline__ void mma16816h(uint32_t* d,
        uint32_t a0, uint32_t a1, uint32_t a2, uint32_t a3,
        uint32_t b0, uint32_t b1) {
    asm volatile("mma.sync.aligned.m16n8k16.row.col.f16.f16.f16.f16 "
                 "{%0,%1}, {%2,%3,%4,%5}, {%6,%7}, {%0,%1};\n"
                 : "+r"(d[0]), "+r"(d[1])
                 : "r"(a0), "r"(a1), "r"(a2), "r"(a3), "r"(b0), "r"(b1));
}

__global__ void __launch_bounds__(NTHREADS, 1)
mlp_kernel(const float* __restrict__ ef, const int* __restrict__ ids,
           const float* __restrict__ W_in, const float* __restrict__ b_in,
           const float* __restrict__ rms_w, const float* __restrict__ W_res,
           const float* __restrict__ b_res, const float* __restrict__ W_out,
           const float* __restrict__ b_out)
{
    extern __shared__ char smem[];
    __half*   Wh   = (__half*)(smem + OFF_W);
    float4*   winb = (float4*)(smem + OFF_WINB);
    uint32_t* brsh = (uint32_t*)(smem + OFF_BRESH);
    float*    wout = (float*)(smem + OFF_WOUT);
    float4*   xs   = (float4*)(smem + OFF_XS);

    const int tid = threadIdx.x;

    /* ---- stage weights once per CTA; fold rms_w (per-k) into W_res ---- */
    for (int idx = tid; idx < NRB * HID * HID; idx += NTHREADS) {
        int i   = idx >> 14;
        int rem = idx & 16383;
        int n   = rem >> 7;
        int k   = rem & 127;
        float w = W_res[idx] * rms_w[i * HID + k];
        Wh[(i * HID + n) * WSTRIDE + k] = __float2half(w);
    }
    for (int c = tid; c < HID; c += NTHREADS) {
        winb[c] = make_float4(W_in[c * 3], W_in[c * 3 + 1], W_in[c * 3 + 2], b_in[c]);
        wout[c] = W_out[c];
    }
    for (int idx = tid; idx < NRB * 64; idx += NTHREADS) {
        int i = idx >> 6, c2 = idx & 63;
        brsh[idx] = pack_h2(b_res[i * HID + 2 * c2], b_res[i * HID + 2 * c2 + 1]);
    }

    const float bout = b_out[0];
    const int warp = tid >> 5, lane = tid & 31;
    const int q = lane & 3, gid = lane >> 2;

    uint32_t wbase = (uint32_t)__cvta_generic_to_shared(Wh);
    /* ldmatrix.x4 rows: lanes 0-7: tile j k[0,8) | 8-15: j k[8,16) |
       16-23: j+1 k[0,8) | 24-31: j+1 k[8,16) */
    uint32_t laneB = wbase +
        ((((lane & 7) + ((lane >> 4) & 1) * 8) * WSTRIDE) + ((lane >> 3) & 1) * 8) * 2;

    /* prefetch first tile's input rows (1 row / thread) */
    float3 xpre = make_float3(0.f, 0.f, 0.f);
    {
        long r = (long)blockIdx.x * TILE_M + tid;
        if (r < N_EDGES) xpre = make_float3(ef[r * 3], ef[r * 3 + 1], ef[r * 3 + 2]);
    }

    for (int tile = blockIdx.x; tile < NTILES; tile += gridDim.x) {
        __syncthreads();
        xs[tid] = make_float4(xpre.x, xpre.y, xpre.z, 0.f);
        __syncthreads();

        /* each warp: rows [warp*32, warp*32+32): sub-tile s2 covers +s2*16 */
        float4 xv[2][2];
        xv[0][0] = xs[warp * 32 + gid];
        xv[0][1] = xs[warp * 32 + gid + 8];
        xv[1][0] = xs[warp * 32 + gid + 16];
        xv[1][1] = xs[warp * 32 + gid + 24];

        /* prefetch next tile while this one computes */
        {
            int nt = tile + gridDim.x;
            xpre = make_float3(0.f, 0.f, 0.f);
            if (nt < NTILES) {
                long r = (long)nt * TILE_M + tid;
                if (r < N_EDGES)
                    xpre = make_float3(ef[r * 3], ef[r * 3 + 1], ef[r * 3 + 2]);
            }
        }

        /* ---- residual stream, packed fp16 A-fragment layout ----
           hp[s2][4*ks+0]=(row gid,  cols 16ks+2q,+1)  [4*ks+1]=(row gid+8, same)
           hp[s2][4*ks+2]=(row gid,  cols 16ks+8+2q,+1)[4*ks+3]=(row gid+8, same) */
        uint32_t hp[2][32];
        float ssf[2][2];
        ssf[0][0] = ssf[0][1] = ssf[1][0] = ssf[1][1] = 0.f;

        /* ---- input layer straight into packed layout (f32 math) ---- */
        #pragma unroll
        for (int j = 0; j < 16; j++) {
            float4 w0 = winb[j * 8 + q * 2];
            float4 w1 = winb[j * 8 + q * 2 + 1];
            int i0 = 4 * (j >> 1) + (j & 1) * 2;
            #pragma unroll
            for (int s2 = 0; s2 < 2; s2++) {
                float4 xa = xv[s2][0], xb = xv[s2][1];
                float n0 = w0.w + xa.x * w0.x + xa.y * w0.y + xa.z * w0.z;
                float n1 = w1.w + xa.x * w1.x + xa.y * w1.y + xa.z * w1.z;
                float n2 = w0.w + xb.x * w0.x + xb.y * w0.y + xb.z * w0.z;
                float n3 = w1.w + xb.x * w1.x + xb.y * w1.y + xb.z * w1.z;
                hp[s2][i0]     = pack_h2(n0, n1);
                hp[s2][i0 + 1] = pack_h2(n2, n3);
                ssf[s2][0] += n0 * n0 + n1 * n1;
                ssf[s2][1] += n2 * n2 + n3 * n3;
            }
        }

        /* ---- 4 residual blocks (f16-accum MMA, all-h2 epilogue) ---- */
        #pragma unroll 1
        for (int blk = 0; blk < NRB; blk++) {
            uint32_t sch[2][2];
            #pragma unroll
            for (int s2 = 0; s2 < 2; s2++)
                #pragma unroll
                for (int g = 0; g < 2; g++) {
                    float v = ssf[s2][g];
                    v += __shfl_xor_sync(0xffffffffu, v, 1);
                    v += __shfl_xor_sync(0xffffffffu, v, 2);
                    float s = rsqrtf(v * (1.f / HID) + RMS_EPS);
                    sch[s2][g] = pack_h2(s, s);
                }

            uint32_t y[2][16][2];
            #pragma unroll
            for (int s2 = 0; s2 < 2; s2++)
                #pragma unroll
                for (int j = 0; j < 16; j++)
                    y[s2][j][0] = y[s2][j][1] = 0u;

            uint32_t lb = laneB + blk * (HID * WSTRIDE * 2);
            #pragma unroll
            for (int ks = 0; ks < 8; ks++) {
                #pragma unroll
                for (int j = 0; j < 16; j += 2) {
                    uint32_t b0, b1, b2, b3;
                    ldsm_x4(b0, b1, b2, b3,
                            lb + (uint32_t)((j * 8 * WSTRIDE + ks * 16) * 2));
                    mma16816h(y[0][j],     hp[0][4*ks], hp[0][4*ks+1], hp[0][4*ks+2], hp[0][4*ks+3], b0, b1);
                    mma16816h(y[0][j + 1], hp[0][4*ks], hp[0][4*ks+1], hp[0][4*ks+2], hp[0][4*ks+3], b2, b3);
                    mma16816h(y[1][j],     hp[1][4*ks], hp[1][4*ks+1], hp[1][4*ks+2], hp[1][4*ks+3], b0, b1);
                    mma16816h(y[1][j + 1], hp[1][4*ks], hp[1][4*ks+1], hp[1][4*ks+2], hp[1][4*ks+3], b2, b3);
                }
            }

            /* pure-h2 epilogue: h += relu(sc*y + b); ss in h2 */
            const uint32_t* bb2 = brsh + blk * 64;
            uint32_t nss[2][2];
            nss[0][0] = nss[0][1] = nss[1][0] = nss[1][1] = 0u;
            #pragma unroll
            for (int j = 0; j < 16; j++) {
                uint32_t bb = bb2[j * 4 + q];
                int i0 = 4 * (j >> 1) + (j & 1) * 2;
                #pragma unroll
                for (int s2 = 0; s2 < 2; s2++) {
                    uint32_t r01 = hmax2z_u(hfma2_u(y[s2][j][0], sch[s2][0], bb));
                    uint32_t r23 = hmax2z_u(hfma2_u(y[s2][j][1], sch[s2][1], bb));
                    hp[s2][i0]     = hadd2_u(hp[s2][i0],     r01);
                    hp[s2][i0 + 1] = hadd2_u(hp[s2][i0 + 1], r23);
                    nss[s2][0] = hfma2_u(hp[s2][i0],     hp[s2][i0],     nss[s2][0]);
                    nss[s2][1] = hfma2_u(hp[s2][i0 + 1], hp[s2][i0 + 1], nss[s2][1]);
                }
            }
            #pragma unroll
            for (int s2 = 0; s2 < 2; s2++)
                #pragma unroll
                for (int g = 0; g < 2; g++) {
                    float2 v = unpack_h2(nss[s2][g]);
                    ssf[s2][g] = v.x + v.y;
                }
        }

        /* ---- output layer (f32) + fused segment-max ---- */
        const float2* w2 = (const float2*)wout;
        #pragma unroll
        for (int s2 = 0; s2 < 2; s2++) {
            float a0 = 0.f, a1 = 0.f;
            #pragma unroll
            for (int j = 0; j < 16; j++) {
                float2 w = w2[j * 4 + q];
                int i0 = 4 * (j >> 1) + (j & 1) * 2;
                float2 hA = unpack_h2(hp[s2][i0]);
                float2 hB = unpack_h2(hp[s2][i0 + 1]);
                a0 += hA.x * w.x + hA.y * w.y;
                a1 += hB.x * w.x + hB.y * w.y;
            }
            a0 += __shfl_xor_sync(0xffffffffu, a0, 1);
            a0 += __shfl_xor_sync(0xffffffffu, a0, 2);
            a1 += __shfl_xor_sync(0xffffffffu, a1, 1);
            a1 += __shfl_xor_sync(0xffffffffu, a1, 2);
            if (q == 0) {
                long r0 = (long)tile * TILE_M + warp * 32 + s2 * 16 + gid;
                long r1 = r0 + 8;
                float l0 = a0 + bout, l1 = a1 + bout;
                if (r0 < N_EDGES) {
                    g_logits[r0] = l0;
                    atomicMax(&g_segmax[ids[r0]], enc_f(l0));
                }
                if (r1 < N_EDGES) {
                    g_logits[r1] = l1;
                    atomicMax(&g_segmax[ids[r1]], enc_f(l1));
                }
            }
        }
    }
}

__global__ void init_kernel() {
    int i = blockIdx.x * blockDim.x + threadIdx.x;
    if (i < NUM_SEGS) { g_segmax[i] = 0u; g_segsum[i] = 0.f; }
}

__global__ void exp_kernel(const int* __restrict__ ids, float* __restrict__ out) {
    int i = blockIdx.x * blockDim.x + threadIdx.x;
    if (i < N_EDGES) {
        int s = ids[i];
        float m = dec_f(g_segmax[s]);
        float e = expf(g_logits[i] - m);
        out[i] = e;
        atomicAdd(&g_segsum[s], e);
    }
}

__global__ void norm_kernel(const int* __restrict__ ids, float* __restrict__ out) {
    int i = blockIdx.x * blockDim.x + threadIdx.x;
    if (i < N_EDGES) out[i] = out[i] / g_segsum[ids[i]];
}

extern "C" void kernel_launch(void* const* d_in, const int* in_sizes, int n_in,
                              void* d_out, int out_size)
{
    const float* ef    = (const float*)d_in[0];
    const int*   ids   = (const int*)d_in[1];
    const float* W_in  = (const float*)d_in[2];
    const float* b_in  = (const float*)d_in[3];
    const float* rms_w = (const float*)d_in[4];
    const float* W_res = (const float*)d_in[5];
    const float* b_res = (const float*)d_in[6];
    const float* W_out = (const float*)d_in[7];
    const float* b_out = (const float*)d_in[8];
    float* out = (float*)d_out;

    cudaFuncSetAttribute(mlp_kernel, cudaFuncAttributeMaxDynamicSharedMemorySize, SMEM_BYTES);

    int dev = 0, sms = 148;
    cudaGetDevice(&dev);
    cudaDeviceGetAttribute(&sms, cudaDevAttrMultiProcessorCount, dev);
    if (sms <= 0) sms = 148;

    init_kernel<<<(NUM_SEGS + 255) / 256, 256>>>();
    mlp_kernel<<<sms, NTHREADS, SMEM_BYTES>>>(ef, ids, W_in, b_in, rms_w,
                                              W_res, b_res, W_out, b_out);
    exp_kernel<<<(N_EDGES + 255) / 256, 256>>>(ids, out);
    norm_kernel<<<(N_EDGES + 255) / 256, 256>>>(ids, out);
}

// round 10
// speedup vs baseline: 1.6574x; 1.0158x over previous
#include <cuda_runtime.h>
#include <cuda_fp16.h>
#include <cstdint>

#define N_EDGES  2000000
#define NUM_SEGS 500000
#define HID      128
#define NRB      4
#define TILE_M   384
#define NTILES   ((N_EDGES + TILE_M - 1) / TILE_M)   /* 5209, last tile 128 rows */
#define NTHREADS 384
#define WSTRIDE  136                  /* halves per W row: 128 + 8 pad */
#define RMS_EPS  1.1920928955078125e-07f

/* SMEM layout (bytes) */
#define OFF_W     0
#define SZ_W      (NRB * HID * WSTRIDE * 2)          /* 139264 */
#define OFF_WINB  (OFF_W + SZ_W)                     /* float4[128] */
#define OFF_BRESH (OFF_WINB + HID * 16)              /* half2[4*64]  */
#define OFF_WOUT  (OFF_BRESH + NRB * 64 * 4)         /* float[128] */
#define OFF_XS    (OFF_WOUT + HID * 4)               /* float4[384] */
#define SMEM_BYTES (OFF_XS + TILE_M * 16)

__device__ float    g_logits[N_EDGES];
__device__ unsigned g_segmax[NUM_SEGS];
__device__ float    g_segsum[NUM_SEGS];

__device__ __forceinline__ unsigned enc_f(float f) {
    unsigned b = __float_as_uint(f);
    return (b & 0x80000000u) ? ~b : (b | 0x80000000u);
}
__device__ __forceinline__ float dec_f(unsigned k) {
    unsigned b = (k & 0x80000000u) ? (k & 0x7FFFFFFFu) : ~k;
    return __uint_as_float(b);
}
__device__ __forceinline__ uint32_t pack_h2(float lo, float hi) {
    __half2 h = __floats2half2_rn(lo, hi);
    return *reinterpret_cast<uint32_t*>(&h);
}
__device__ __forceinline__ float2 unpack_h2(uint32_t u) {
    return __half22float2(*reinterpret_cast<__half2*>(&u));
}
__device__ __forceinline__ uint32_t hadd2_u(uint32_t a, uint32_t b) {
    __half2 r = __hadd2(*reinterpret_cast<__half2*>(&a), *reinterpret_cast<__half2*>(&b));
    return *reinterpret_cast<uint32_t*>(&r);
}
__device__ __forceinline__ uint32_t hmax2z_u(uint32_t a) {
    __half2 z = __float2half2_rn(0.f);
    __half2 r = __hmax2(*reinterpret_cast<__half2*>(&a), z);
    return *reinterpret_cast<uint32_t*>(&r);
}
__device__ __forceinline__ uint32_t hfma2_u(uint32_t a, uint32_t b, uint32_t c) {
    __half2 r = __hfma2(*reinterpret_cast<__half2*>(&a),
                        *reinterpret_cast<__half2*>(&b),
                        *reinterpret_cast<__half2*>(&c));
    return *reinterpret_cast<uint32_t*>(&r);
}
__device__ __forceinline__ void ldsm_x4(uint32_t& r0, uint32_t& r1, uint32_t& r2, uint32_t& r3,
                                        uint32_t addr) {
    asm volatile("ldmatrix.sync.aligned.m8n8.x4.shared.b16 {%0,%1,%2,%3}, [%4];\n"
                 : "=r"(r0), "=r"(r1), "=r"(r2), "=r"(r3) : "r"(addr));
}
/* f16 accumulator variant: d = {d0,d1} half2 regs.
   d0 = (row gid, cols 8j+2q,+1), d1 = (row gid+8, same cols) */
__device__ __forceinline__ void mma16816h(uint32_t* d,
        uint32_t a0, uint32_t a1, uint32_t a2, uint32_t a3,
        uint32_t b0, uint32_t b1) {
    asm volatile("mma.sync.aligned.m16n8k16.row.col.f16.f16.f16.f16 "
                 "{%0,%1}, {%2,%3,%4,%5}, {%6,%7}, {%0,%1};\n"
                 : "+r"(d[0]), "+r"(d[1])
                 : "r"(a0), "r"(a1), "r"(a2), "r"(a3), "r"(b0), "r"(b1));
}

__global__ void __launch_bounds__(NTHREADS, 1)
mlp_kernel(const float* __restrict__ ef, const int* __restrict__ ids,
           const float* __restrict__ W_in, const float* __restrict__ b_in,
           const float* __restrict__ rms_w, const float* __restrict__ W_res,
           const float* __restrict__ b_res, const float* __restrict__ W_out,
           const float* __restrict__ b_out)
{
    extern __shared__ char smem[];
    __half*   Wh   = (__half*)(smem + OFF_W);
    float4*   winb = (float4*)(smem + OFF_WINB);
    uint32_t* brsh = (uint32_t*)(smem + OFF_BRESH);
    float*    wout = (float*)(smem + OFF_WOUT);
    float4*   xs   = (float4*)(smem + OFF_XS);

    const int tid = threadIdx.x;

    /* ---- stage weights once per CTA; fold rms_w (per-k) into W_res ---- */
    for (int idx = tid; idx < NRB * HID * HID; idx += NTHREADS) {
        int i   = idx >> 14;
        int rem = idx & 16383;
        int n   = rem >> 7;
        int k   = rem & 127;
        float w = W_res[idx] * rms_w[i * HID + k];
        Wh[(i * HID + n) * WSTRIDE + k] = __float2half(w);
    }
    for (int c = tid; c < HID; c += NTHREADS) {
        winb[c] = make_float4(W_in[c * 3], W_in[c * 3 + 1], W_in[c * 3 + 2], b_in[c]);
        wout[c] = W_out[c];
    }
    for (int idx = tid; idx < NRB * 64; idx += NTHREADS) {
        int i = idx >> 6, c2 = idx & 63;
        brsh[idx] = pack_h2(b_res[i * HID + 2 * c2], b_res[i * HID + 2 * c2 + 1]);
    }

    const float bout = b_out[0];
    const int warp = tid >> 5, lane = tid & 31;
    const int q = lane & 3, gid = lane >> 2;

    uint32_t wbase = (uint32_t)__cvta_generic_to_shared(Wh);
    /* ldmatrix.x4 rows: lanes 0-7: tile j k[0,8) | 8-15: j k[8,16) |
       16-23: j+1 k[0,8) | 24-31: j+1 k[8,16) */
    uint32_t laneB = wbase +
        ((((lane & 7) + ((lane >> 4) & 1) * 8) * WSTRIDE) + ((lane >> 3) & 1) * 8) * 2;

    /* prefetch first tile's input rows (1 row / thread) */
    float3 xpre = make_float3(0.f, 0.f, 0.f);
    {
        long r = (long)blockIdx.x * TILE_M + tid;
        if (r < N_EDGES) xpre = make_float3(ef[r * 3], ef[r * 3 + 1], ef[r * 3 + 2]);
    }

    for (int tile = blockIdx.x; tile < NTILES; tile += gridDim.x) {
        __syncthreads();
        xs[tid] = make_float4(xpre.x, xpre.y, xpre.z, 0.f);
        __syncthreads();

        /* each warp: rows [warp*32, warp*32+32): sub-tile s2 covers +s2*16 */
        float4 xv[2][2];
        xv[0][0] = xs[warp * 32 + gid];
        xv[0][1] = xs[warp * 32 + gid + 8];
        xv[1][0] = xs[warp * 32 + gid + 16];
        xv[1][1] = xs[warp * 32 + gid + 24];

        /* prefetch next tile while this one computes */
        {
            int nt = tile + gridDim.x;
            xpre = make_float3(0.f, 0.f, 0.f);
            if (nt < NTILES) {
                long r = (long)nt * TILE_M + tid;
                if (r < N_EDGES)
                    xpre = make_float3(ef[r * 3], ef[r * 3 + 1], ef[r * 3 + 2]);
            }
        }

        /* ---- residual stream, packed fp16 A-fragment layout ----
           hp[s2][4*ks+0]=(row gid,  cols 16ks+2q,+1)  [4*ks+1]=(row gid+8, same)
           hp[s2][4*ks+2]=(row gid,  cols 16ks+8+2q,+1)[4*ks+3]=(row gid+8, same) */
        uint32_t hp[2][32];
        float ssf[2][2];
        ssf[0][0] = ssf[0][1] = ssf[1][0] = ssf[1][1] = 0.f;

        /* ---- input layer straight into packed layout (f32 math) ---- */
        #pragma unroll
        for (int j = 0; j < 16; j++) {
            float4 w0 = winb[j * 8 + q * 2];
            float4 w1 = winb[j * 8 + q * 2 + 1];
            int i0 = 4 * (j >> 1) + (j & 1) * 2;
            #pragma unroll
            for (int s2 = 0; s2 < 2; s2++) {
                float4 xa = xv[s2][0], xb = xv[s2][1];
                float n0 = w0.w + xa.x * w0.x + xa.y * w0.y + xa.z * w0.z;
                float n1 = w1.w + xa.x * w1.x + xa.y * w1.y + xa.z * w1.z;
                float n2 = w0.w + xb.x * w0.x + xb.y * w0.y + xb.z * w0.z;
                float n3 = w1.w + xb.x * w1.x + xb.y * w1.y + xb.z * w1.z;
                hp[s2][i0]     = pack_h2(n0, n1);
                hp[s2][i0 + 1] = pack_h2(n2, n3);
                ssf[s2][0] += n0 * n0 + n1 * n1;
                ssf[s2][1] += n2 * n2 + n3 * n3;
            }
        }

        /* ---- 4 residual blocks (f16-accum MMA, all-h2 epilogue) ---- */
        #pragma unroll 1
        for (int blk = 0; blk < NRB; blk++) {
            uint32_t sch[2][2];
            #pragma unroll
            for (int s2 = 0; s2 < 2; s2++)
                #pragma unroll
                for (int g = 0; g < 2; g++) {
                    float v = ssf[s2][g];
                    v += __shfl_xor_sync(0xffffffffu, v, 1);
                    v += __shfl_xor_sync(0xffffffffu, v, 2);
                    float s = rsqrtf(v * (1.f / HID) + RMS_EPS);
                    sch[s2][g] = pack_h2(s, s);
                }

            uint32_t y[2][16][2];
            #pragma unroll
            for (int s2 = 0; s2 < 2; s2++)
                #pragma unroll
                for (int j = 0; j < 16; j++)
                    y[s2][j][0] = y[s2][j][1] = 0u;

            uint32_t lb = laneB + blk * (HID * WSTRIDE * 2);
            #pragma unroll
            for (int ks = 0; ks < 8; ks++) {
                #pragma unroll
                for (int j = 0; j < 16; j += 2) {
                    uint32_t b0, b1, b2, b3;
                    ldsm_x4(b0, b1, b2, b3,
                            lb + (uint32_t)((j * 8 * WSTRIDE + ks * 16) * 2));
                    mma16816h(y[0][j],     hp[0][4*ks], hp[0][4*ks+1], hp[0][4*ks+2], hp[0][4*ks+3], b0, b1);
                    mma16816h(y[0][j + 1], hp[0][4*ks], hp[0][4*ks+1], hp[0][4*ks+2], hp[0][4*ks+3], b2, b3);
                    mma16816h(y[1][j],     hp[1][4*ks], hp[1][4*ks+1], hp[1][4*ks+2], hp[1][4*ks+3], b0, b1);
                    mma16816h(y[1][j + 1], hp[1][4*ks], hp[1][4*ks+1], hp[1][4*ks+2], hp[1][4*ks+3], b2, b3);
                }
            }

            /* pure-h2 epilogue: h += relu(sc*y + b); ss in h2 */
            const uint32_t* bb2 = brsh + blk * 64;
            uint32_t nss[2][2];
            nss[0][0] = nss[0][1] = nss[1][0] = nss[1][1] = 0u;
            #pragma unroll
            for (int j = 0; j < 16; j++) {
                uint32_t bb = bb2[j * 4 + q];
                int i0 = 4 * (j >> 1) + (j & 1) * 2;
                #pragma unroll
                for (int s2 = 0; s2 < 2; s2++) {
                    uint32_t r01 = hmax2z_u(hfma2_u(y[s2][j][0], sch[s2][0], bb));
                    uint32_t r23 = hmax2z_u(hfma2_u(y[s2][j][1], sch[s2][1], bb));
                    hp[s2][i0]     = hadd2_u(hp[s2][i0],     r01);
                    hp[s2][i0 + 1] = hadd2_u(hp[s2][i0 + 1], r23);
                    nss[s2][0] = hfma2_u(hp[s2][i0],     hp[s2][i0],     nss[s2][0]);
                    nss[s2][1] = hfma2_u(hp[s2][i0 + 1], hp[s2][i0 + 1], nss[s2][1]);
                }
            }
            #pragma unroll
            for (int s2 = 0; s2 < 2; s2++)
                #pragma unroll
                for (int g = 0; g < 2; g++) {
                    float2 v = unpack_h2(nss[s2][g]);
                    ssf[s2][g] = v.x + v.y;
                }
        }

        /* ---- output layer (f32) + fused segment-max ---- */
        const float2* w2 = (const float2*)wout;
        #pragma unroll
        for (int s2 = 0; s2 < 2; s2++) {
            float a0 = 0.f, a1 = 0.f;
            #pragma unroll
            for (int j = 0; j < 16; j++) {
                float2 w = w2[j * 4 + q];
                int i0 = 4 * (j >> 1) + (j & 1) * 2;
                float2 hA = unpack_h2(hp[s2][i0]);
                float2 hB = unpack_h2(hp[s2][i0 + 1]);
                a0 += hA.x * w.x + hA.y * w.y;
                a1 += hB.x * w.x + hB.y * w.y;
            }
            a0 += __shfl_xor_sync(0xffffffffu, a0, 1);
            a0 += __shfl_xor_sync(0xffffffffu, a0, 2);
            a1 += __shfl_xor_sync(0xffffffffu, a1, 1);
            a1 += __shfl_xor_sync(0xffffffffu, a1, 2);
            if (q == 0) {
                long r0 = (long)tile * TILE_M + warp * 32 + s2 * 16 + gid;
                long r1 = r0 + 8;
                float l0 = a0 + bout, l1 = a1 + bout;
                if (r0 < N_EDGES) {
                    g_logits[r0] = l0;
                    atomicMax(&g_segmax[ids[r0]], enc_f(l0));
                }
                if (r1 < N_EDGES) {
                    g_logits[r1] = l1;
                    atomicMax(&g_segmax[ids[r1]], enc_f(l1));
                }
            }
        }
    }
}

__global__ void init_kernel() {
    int i = blockIdx.x * blockDim.x + threadIdx.x;
    if (i < NUM_SEGS) { g_segmax[i] = 0u; g_segsum[i] = 0.f; }
}

__global__ void exp_kernel(const int* __restrict__ ids, float* __restrict__ out) {
    int i = blockIdx.x * blockDim.x + threadIdx.x;
    if (i < N_EDGES) {
        int s = ids[i];
        float m = dec_f(g_segmax[s]);
        float e = expf(g_logits[i] - m);
        out[i] = e;
        atomicAdd(&g_segsum[s], e);
    }
}

__global__ void norm_kernel(const int* __restrict__ ids, float* __restrict__ out) {
    int i = blockIdx.x * blockDim.x + threadIdx.x;
    if (i < N_EDGES) out[i] = out[i] / g_segsum[ids[i]];
}

extern "C" void kernel_launch(void* const* d_in, const int* in_sizes, int n_in,
                              void* d_out, int out_size)
{
    const float* ef    = (const float*)d_in[0];
    const int*   ids   = (const int*)d_in[1];
    const float* W_in  = (const float*)d_in[2];
    const float* b_in  = (const float*)d_in[3];
    const float* rms_w = (const float*)d_in[4];
    const float* W_res = (const float*)d_in[5];
    const float* b_res = (const float*)d_in[6];
    const float* W_out = (const float*)d_in[7];
    const float* b_out = (const float*)d_in[8];
    float* out = (float*)d_out;

    cudaFuncSetAttribute(mlp_kernel, cudaFuncAttributeMaxDynamicSharedMemorySize, SMEM_BYTES);

    int dev = 0, sms = 148;
    cudaGetDevice(&dev);
    cudaDeviceGetAttribute(&sms, cudaDevAttrMultiProcessorCount, dev);
    if (sms <= 0) sms = 148;

    init_kernel<<<(NUM_SEGS + 255) / 256, 256>>>();
    mlp_kernel<<<sms, NTHREADS, SMEM_BYTES>>>(ef, ids, W_in, b_in, rms_w,
                                              W_res, b_res, W_out, b_out);
    exp_kernel<<<(N_EDGES + 255) / 256, 256>>>(ids, out);
    norm_kernel<<<(N_EDGES + 255) / 256, 256>>>(ids, out);
}

// round 11
// speedup vs baseline: 1.7389x; 1.0492x over previous
#include <cuda_runtime.h>
#include <cuda_fp16.h>
#include <cstdint>

#define N_EDGES  2000000
#define NUM_SEGS 500000
#define HID      128
#define NRB      4
#define TILE_M   384
#define NTILES   ((N_EDGES + TILE_M - 1) / TILE_M)   /* 5209, last tile 128 rows */
#define NTHREADS 384
#define WSTRIDE  136                  /* halves per W row: 128 + 8 pad */
#define WINSTR   24                   /* halves per W_in row: 16 + 8 pad */
#define RMS_EPS  1.1920928955078125e-07f

/* SMEM layout (bytes) */
#define OFF_W     0
#define SZ_W      (NRB * HID * WSTRIDE * 2)          /* 139264 */
#define OFF_WIN16 (OFF_W + SZ_W)                     /* half[128*24] ldsm layout */
#define OFF_BRESH (OFF_WIN16 + HID * WINSTR * 2)     /* half2[4*64]  */
#define OFF_WOUT  (OFF_BRESH + NRB * 64 * 4)         /* float[128] */
#define OFF_XS    (OFF_WOUT + HID * 4)               /* float4[384] */
#define SMEM_BYTES (OFF_XS + TILE_M * 16)

__device__ float    g_logits[N_EDGES];
__device__ unsigned g_segmax[NUM_SEGS];
__device__ float    g_segsum[NUM_SEGS];

__device__ __forceinline__ unsigned enc_f(float f) {
    unsigned b = __float_as_uint(f);
    return (b & 0x80000000u) ? ~b : (b | 0x80000000u);
}
__device__ __forceinline__ float dec_f(unsigned k) {
    unsigned b = (k & 0x80000000u) ? (k & 0x7FFFFFFFu) : ~k;
    return __uint_as_float(b);
}
__device__ __forceinline__ uint32_t pack_h2(float lo, float hi) {
    __half2 h = __floats2half2_rn(lo, hi);
    return *reinterpret_cast<uint32_t*>(&h);
}
__device__ __forceinline__ float2 unpack_h2(uint32_t u) {
    return __half22float2(*reinterpret_cast<__half2*>(&u));
}
__device__ __forceinline__ uint32_t hadd2_u(uint32_t a, uint32_t b) {
    __half2 r = __hadd2(*reinterpret_cast<__half2*>(&a), *reinterpret_cast<__half2*>(&b));
    return *reinterpret_cast<uint32_t*>(&r);
}
__device__ __forceinline__ uint32_t hmax2z_u(uint32_t a) {
    __half2 z = __float2half2_rn(0.f);
    __half2 r = __hmax2(*reinterpret_cast<__half2*>(&a), z);
    return *reinterpret_cast<uint32_t*>(&r);
}
__device__ __forceinline__ uint32_t hfma2_u(uint32_t a, uint32_t b, uint32_t c) {
    __half2 r = __hfma2(*reinterpret_cast<__half2*>(&a),
                        *reinterpret_cast<__half2*>(&b),
                        *reinterpret_cast<__half2*>(&c));
    return *reinterpret_cast<uint32_t*>(&r);
}
__device__ __forceinline__ void ldsm_x4(uint32_t& r0, uint32_t& r1, uint32_t& r2, uint32_t& r3,
                                        uint32_t addr) {
    asm volatile("ldmatrix.sync.aligned.m8n8.x4.shared.b16 {%0,%1,%2,%3}, [%4];\n"
                 : "=r"(r0), "=r"(r1), "=r"(r2), "=r"(r3) : "r"(addr));
}
/* f16 accumulator variant: d = {d0,d1} half2 regs.
   d0 = (row gid, cols 8j+2q,+1), d1 = (row gid+8, same cols) */
__device__ __forceinline__ void mma16816h(uint32_t* d,
        uint32_t a0, uint32_t a1, uint32_t a2, uint32_t a3,
        uint32_t b0, uint32_t b1) {
    asm volatile("mma.sync.aligned.m16n8k16.row.col.f16.f16.f16.f16 "
                 "{%0,%1}, {%2,%3,%4,%5}, {%6,%7}, {%0,%1};\n"
                 : "+r"(d[0]), "+r"(d[1])
                 : "r"(a0), "r"(a1), "r"(a2), "r"(a3), "r"(b0), "r"(b1));
}

__global__ void __launch_bounds__(NTHREADS, 1)
mlp_kernel(const float* __restrict__ ef, const int* __restrict__ ids,
           const float* __restrict__ W_in, const float* __restrict__ b_in,
           const float* __restrict__ rms_w, const float* __restrict__ W_res,
           const float* __restrict__ b_res, const float* __restrict__ W_out,
           const float* __restrict__ b_out)
{
    extern __shared__ char smem[];
    __half*   Wh   = (__half*)(smem + OFF_W);
    __half*   winh = (__half*)(smem + OFF_WIN16);
    uint32_t* brsh = (uint32_t*)(smem + OFF_BRESH);
    float*    wout = (float*)(smem + OFF_WOUT);
    float4*   xs   = (float4*)(smem + OFF_XS);

    const int tid = threadIdx.x;

    /* ---- stage weights once per CTA; fold rms_w (per-k) into W_res ---- */
    for (int idx = tid; idx < NRB * HID * HID; idx += NTHREADS) {
        int i   = idx >> 14;
        int rem = idx & 16383;
        int n   = rem >> 7;
        int k   = rem & 127;
        float w = W_res[idx] * rms_w[i * HID + k];
        Wh[(i * HID + n) * WSTRIDE + k] = __float2half(w);
    }
    /* W_in in ldsm layout: row n, k=0..2 weights, k=3 bias, k=4..15 zero */
    for (int idx = tid; idx < HID * 16; idx += NTHREADS) {
        int n = idx >> 4, k = idx & 15;
        float v = (k < 3) ? W_in[n * 3 + k] : (k == 3 ? b_in[n] : 0.f);
        winh[n * WINSTR + k] = __float2half(v);
    }
    for (int idx = tid; idx < HID * (WINSTR - 16); idx += NTHREADS) {
        int n = idx / (WINSTR - 16), k = 16 + idx % (WINSTR - 16);
        winh[n * WINSTR + k] = __float2half(0.f);   /* pad region */
    }
    for (int c = tid; c < HID; c += NTHREADS) wout[c] = W_out[c];
    for (int idx = tid; idx < NRB * 64; idx += NTHREADS) {
        int i = idx >> 6, c2 = idx & 63;
        brsh[idx] = pack_h2(b_res[i * HID + 2 * c2], b_res[i * HID + 2 * c2 + 1]);
    }

    const float bout = b_out[0];
    const int warp = tid >> 5, lane = tid & 31;
    const int q = lane & 3, gid = lane >> 2;

    uint32_t wbase = (uint32_t)__cvta_generic_to_shared(Wh);
    uint32_t laneB = wbase +
        ((((lane & 7) + ((lane >> 4) & 1) * 8) * WSTRIDE) + ((lane >> 3) & 1) * 8) * 2;
    uint32_t wibase = (uint32_t)__cvta_generic_to_shared(winh);
    uint32_t laneWi = wibase +
        ((((lane & 7) + ((lane >> 4) & 1) * 8) * WINSTR) + ((lane >> 3) & 1) * 8) * 2;

    /* prefetch first tile's input rows (1 row / thread) */
    float3 xpre = make_float3(0.f, 0.f, 0.f);
    {
        long r = (long)blockIdx.x * TILE_M + tid;
        if (r < N_EDGES) xpre = make_float3(ef[r * 3], ef[r * 3 + 1], ef[r * 3 + 2]);
    }

    for (int tile = blockIdx.x; tile < NTILES; tile += gridDim.x) {
        __syncthreads();
        xs[tid] = make_float4(xpre.x, xpre.y, xpre.z, 0.f);
        __syncthreads();

        /* each warp: rows [warp*32, warp*32+32): sub-tile s2 covers +s2*16 */
        float4 xv[2][2];
        xv[0][0] = xs[warp * 32 + gid];
        xv[0][1] = xs[warp * 32 + gid + 8];
        xv[1][0] = xs[warp * 32 + gid + 16];
        xv[1][1] = xs[warp * 32 + gid + 24];

        /* prefetch next tile while this one computes */
        {
            int nt = tile + gridDim.x;
            xpre = make_float3(0.f, 0.f, 0.f);
            if (nt < NTILES) {
                long r = (long)nt * TILE_M + tid;
                if (r < N_EDGES)
                    xpre = make_float3(ef[r * 3], ef[r * 3 + 1], ef[r * 3 + 2]);
            }
        }

        /* ---- residual stream, packed fp16 A-fragment layout ----
           hp[s2][4*ks+0]=(row gid,  cols 16ks+2q,+1)  [4*ks+1]=(row gid+8, same)
           hp[s2][4*ks+2]=(row gid,  cols 16ks+8+2q,+1)[4*ks+3]=(row gid+8, same) */
        uint32_t hp[2][32];
        #pragma unroll
        for (int s2 = 0; s2 < 2; s2++)
            #pragma unroll
            for (int i = 0; i < 32; i++) hp[s2][i] = 0u;

        /* ---- input layer on the tensor pipe ----
           A frag (k=16): k0..2 = x, k3 = 1.0 (bias), k4..15 = 0 */
        {
            uint32_t a0[2], a1[2];
            #pragma unroll
            for (int s2 = 0; s2 < 2; s2++) {
                float4 xa = xv[s2][0], xb = xv[s2][1];
                a0[s2] = (q == 0) ? pack_h2(xa.x, xa.y) : (q == 1) ? pack_h2(xa.z, 1.f) : 0u;
                a1[s2] = (q == 0) ? pack_h2(xb.x, xb.y) : (q == 1) ? pack_h2(xb.z, 1.f) : 0u;
            }
            #pragma unroll
            for (int jp = 0; jp < 8; jp++) {
                uint32_t b0, b1, b2, b3;
                ldsm_x4(b0, b1, b2, b3, laneWi + (uint32_t)(jp * 16 * WINSTR * 2));
                #pragma unroll
                for (int s2 = 0; s2 < 2; s2++) {
                    int j0 = 2 * jp, j1 = 2 * jp + 1;
                    int i00 = 4 * (j0 >> 1) + (j0 & 1) * 2;
                    int i01 = 4 * (j1 >> 1) + (j1 & 1) * 2;
                    mma16816h(&hp[s2][i00], a0[s2], a1[s2], 0u, 0u, b0, b1);
                    mma16816h(&hp[s2][i01], a0[s2], a1[s2], 0u, 0u, b2, b3);
                }
            }
        }

        /* sum of squares of h (rows gid = even hp, gid+8 = odd) */
        float ssf[2][2];
        #pragma unroll
        for (int s2 = 0; s2 < 2; s2++) {
            uint32_t n0 = 0u, n1 = 0u;
            #pragma unroll
            for (int i = 0; i < 16; i++) {
                n0 = hfma2_u(hp[s2][2 * i],     hp[s2][2 * i],     n0);
                n1 = hfma2_u(hp[s2][2 * i + 1], hp[s2][2 * i + 1], n1);
            }
            float2 v0 = unpack_h2(n0), v1 = unpack_h2(n1);
            ssf[s2][0] = v0.x + v0.y;
            ssf[s2][1] = v1.x + v1.y;
        }

        /* ---- 4 residual blocks: j-pair-outer so relu overlaps next pair's MMAs ---- */
        #pragma unroll 1
        for (int blk = 0; blk < NRB; blk++) {
            uint32_t sch[2][2];
            #pragma unroll
            for (int s2 = 0; s2 < 2; s2++)
                #pragma unroll
                for (int g = 0; g < 2; g++) {
                    float v = ssf[s2][g];
                    v += __shfl_xor_sync(0xffffffffu, v, 1);
                    v += __shfl_xor_sync(0xffffffffu, v, 2);
                    float s = rsqrtf(v * (1.f / HID) + RMS_EPS);
                    sch[s2][g] = pack_h2(s, s);
                }

            uint32_t y[2][16][2];   /* holds relu(sc*acc + b) after each pair */
            uint32_t lb = laneB + blk * (HID * WSTRIDE * 2);
            const uint32_t* bb2 = brsh + blk * 64;

            #pragma unroll
            for (int jp = 0; jp < 8; jp++) {
                int j0 = 2 * jp, j1 = 2 * jp + 1;
                y[0][j0][0] = y[0][j0][1] = y[0][j1][0] = y[0][j1][1] = 0u;
                y[1][j0][0] = y[1][j0][1] = y[1][j1][0] = y[1][j1][1] = 0u;
                #pragma unroll
                for (int ks = 0; ks < 8; ks++) {
                    uint32_t b0, b1, b2, b3;
                    ldsm_x4(b0, b1, b2, b3,
                            lb + (uint32_t)((jp * 16 * WSTRIDE + ks * 16) * 2));
                    mma16816h(y[0][j0], hp[0][4*ks], hp[0][4*ks+1], hp[0][4*ks+2], hp[0][4*ks+3], b0, b1);
                    mma16816h(y[0][j1], hp[0][4*ks], hp[0][4*ks+1], hp[0][4*ks+2], hp[0][4*ks+3], b2, b3);
                    mma16816h(y[1][j0], hp[1][4*ks], hp[1][4*ks+1], hp[1][4*ks+2], hp[1][4*ks+3], b0, b1);
                    mma16816h(y[1][j1], hp[1][4*ks], hp[1][4*ks+1], hp[1][4*ks+2], hp[1][4*ks+3], b2, b3);
                }
                /* relu(sc*y + b) in place — overlaps next pair's ldsm/mma stream */
                uint32_t bbA = bb2[j0 * 4 + q], bbB = bb2[j1 * 4 + q];
                #pragma unroll
                for (int s2 = 0; s2 < 2; s2++) {
                    y[s2][j0][0] = hmax2z_u(hfma2_u(y[s2][j0][0], sch[s2][0], bbA));
                    y[s2][j0][1] = hmax2z_u(hfma2_u(y[s2][j0][1], sch[s2][1], bbA));
                    y[s2][j1][0] = hmax2z_u(hfma2_u(y[s2][j1][0], sch[s2][0], bbB));
                    y[s2][j1][1] = hmax2z_u(hfma2_u(y[s2][j1][1], sch[s2][1], bbB));
                }
            }

            /* commit residual + next sum-of-squares */
            #pragma unroll
            for (int s2 = 0; s2 < 2; s2++) {
                uint32_t n0 = 0u, n1 = 0u;
                #pragma unroll
                for (int j = 0; j < 16; j++) {
                    int i0 = 4 * (j >> 1) + (j & 1) * 2;
                    hp[s2][i0]     = hadd2_u(hp[s2][i0],     y[s2][j][0]);
                    hp[s2][i0 + 1] = hadd2_u(hp[s2][i0 + 1], y[s2][j][1]);
                    n0 = hfma2_u(hp[s2][i0],     hp[s2][i0],     n0);
                    n1 = hfma2_u(hp[s2][i0 + 1], hp[s2][i0 + 1], n1);
                }
                float2 v0 = unpack_h2(n0), v1 = unpack_h2(n1);
                ssf[s2][0] = v0.x + v0.y;
                ssf[s2][1] = v1.x + v1.y;
            }
        }

        /* ---- output layer (f32) + fused segment-max ---- */
        const float2* w2 = (const float2*)wout;
        #pragma unroll
        for (int s2 = 0; s2 < 2; s2++) {
            float a0 = 0.f, a1 = 0.f;
            #pragma unroll
            for (int j = 0; j < 16; j++) {
                float2 w = w2[j * 4 + q];
                int i0 = 4 * (j >> 1) + (j & 1) * 2;
                float2 hA = unpack_h2(hp[s2][i0]);
                float2 hB = unpack_h2(hp[s2][i0 + 1]);
                a0 += hA.x * w.x + hA.y * w.y;
                a1 += hB.x * w.x + hB.y * w.y;
            }
            a0 += __shfl_xor_sync(0xffffffffu, a0, 1);
            a0 += __shfl_xor_sync(0xffffffffu, a0, 2);
            a1 += __shfl_xor_sync(0xffffffffu, a1, 1);
            a1 += __shfl_xor_sync(0xffffffffu, a1, 2);
            if (q == 0) {
                long r0 = (long)tile * TILE_M + warp * 32 + s2 * 16 + gid;
                long r1 = r0 + 8;
                float l0 = a0 + bout, l1 = a1 + bout;
                if (r0 < N_EDGES) {
                    g_logits[r0] = l0;
                    atomicMax(&g_segmax[ids[r0]], enc_f(l0));
                }
                if (r1 < N_EDGES) {
                    g_logits[r1] = l1;
                    atomicMax(&g_segmax[ids[r1]], enc_f(l1));
                }
            }
        }
    }
}

__global__ void init_kernel() {
    int i = blockIdx.x * blockDim.x + threadIdx.x;
    if (i < NUM_SEGS) { g_segmax[i] = 0u; g_segsum[i] = 0.f; }
}

__global__ void exp_kernel(const int* __restrict__ ids, float* __restrict__ out) {
    int i = blockIdx.x * blockDim.x + threadIdx.x;
    if (i < N_EDGES) {
        int s = ids[i];
        float m = dec_f(g_segmax[s]);
        float e = expf(g_logits[i] - m);
        out[i] = e;
        atomicAdd(&g_segsum[s], e);
    }
}

__global__ void norm_kernel(const int* __restrict__ ids, float* __restrict__ out) {
    int i = blockIdx.x * blockDim.x + threadIdx.x;
    if (i < N_EDGES) out[i] = out[i] / g_segsum[ids[i]];
}

extern "C" void kernel_launch(void* const* d_in, const int* in_sizes, int n_in,
                              void* d_out, int out_size)
{
    const float* ef    = (const float*)d_in[0];
    const int*   ids   = (const int*)d_in[1];
    const float* W_in  = (const float*)d_in[2];
    const float* b_in  = (const float*)d_in[3];
    const float* rms_w = (const float*)d_in[4];
    const float* W_res = (const float*)d_in[5];
    const float* b_res = (const float*)d_in[6];
    const float* W_out = (const float*)d_in[7];
    const float* b_out = (const float*)d_in[8];
    float* out = (float*)d_out;

    cudaFuncSetAttribute(mlp_kernel, cudaFuncAttributeMaxDynamicSharedMemorySize, SMEM_BYTES);

    int dev = 0, sms = 148;
    cudaGetDevice(&dev);
    cudaDeviceGetAttribute(&sms, cudaDevAttrMultiProcessorCount, dev);
    if (sms <= 0) sms = 148;

    init_kernel<<<(NUM_SEGS + 255) / 256, 256>>>();
    mlp_kernel<<<sms, NTHREADS, SMEM_BYTES>>>(ef, ids, W_in, b_in, rms_w,
                                              W_res, b_res, W_out, b_out);
    exp_kernel<<<(N_EDGES + 255) / 256, 256>>>(ids, out);
    norm_kernel<<<(N_EDGES + 255) / 256, 256>>>(ids, out);
}

// round 12
// speedup vs baseline: 1.8477x; 1.0626x over previous
#include <cuda_runtime.h>
#include <cuda_fp16.h>
#include <cstdint>

#define N_EDGES  2000000
#define NUM_SEGS 500000
#define HID      128
#define NRB      4
#define TILE_M   384
#define NTILES   ((N_EDGES + TILE_M - 1) / TILE_M)   /* 5209, last tile 128 rows */
#define NTHREADS 384
#define WSTRIDE  136                  /* halves per W row: 128 + 8 pad */
#define WINSTR   24                   /* halves per W_in row: 16 + 8 pad */
#define RMS_EPS  1.1920928955078125e-07f

/* SMEM layout (bytes) */
#define OFF_W     0
#define SZ_W      (NRB * HID * WSTRIDE * 2)          /* 139264 */
#define OFF_WIN16 (OFF_W + SZ_W)                     /* half[128*24] ldsm layout */
#define OFF_BRESH (OFF_WIN16 + HID * WINSTR * 2)     /* half2[4*64]  */
#define OFF_WOUT  (OFF_BRESH + NRB * 64 * 4)         /* float[128] */
#define SMEM_BYTES (OFF_WOUT + HID * 4)

__device__ float    g_logits[N_EDGES];
__device__ unsigned g_segmax[NUM_SEGS];
__device__ float    g_segsum[NUM_SEGS];

__device__ __forceinline__ unsigned enc_f(float f) {
    unsigned b = __float_as_uint(f);
    return (b & 0x80000000u) ? ~b : (b | 0x80000000u);
}
__device__ __forceinline__ float dec_f(unsigned k) {
    unsigned b = (k & 0x80000000u) ? (k & 0x7FFFFFFFu) : ~k;
    return __uint_as_float(b);
}
__device__ __forceinline__ uint32_t pack_h2(float lo, float hi) {
    __half2 h = __floats2half2_rn(lo, hi);
    return *reinterpret_cast<uint32_t*>(&h);
}
__device__ __forceinline__ float2 unpack_h2(uint32_t u) {
    return __half22float2(*reinterpret_cast<__half2*>(&u));
}
__device__ __forceinline__ uint32_t hadd2_u(uint32_t a, uint32_t b) {
    __half2 r = __hadd2(*reinterpret_cast<__half2*>(&a), *reinterpret_cast<__half2*>(&b));
    return *reinterpret_cast<uint32_t*>(&r);
}
__device__ __forceinline__ uint32_t hmax2z_u(uint32_t a) {
    __half2 z = __float2half2_rn(0.f);
    __half2 r = __hmax2(*reinterpret_cast<__half2*>(&a), z);
    return *reinterpret_cast<uint32_t*>(&r);
}
__device__ __forceinline__ uint32_t hfma2_u(uint32_t a, uint32_t b, uint32_t c) {
    __half2 r = __hfma2(*reinterpret_cast<__half2*>(&a),
                        *reinterpret_cast<__half2*>(&b),
                        *reinterpret_cast<__half2*>(&c));
    return *reinterpret_cast<uint32_t*>(&r);
}
__device__ __forceinline__ void ldsm_x4(uint32_t& r0, uint32_t& r1, uint32_t& r2, uint32_t& r3,
                                        uint32_t addr) {
    asm volatile("ldmatrix.sync.aligned.m8n8.x4.shared.b16 {%0,%1,%2,%3}, [%4];\n"
                 : "=r"(r0), "=r"(r1), "=r"(r2), "=r"(r3) : "r"(addr));
}
/* f16 accumulator variant: d = {d0,d1} half2 regs.
   d0 = (row gid, cols 8j+2q,+1), d1 = (row gid+8, same cols) */
__device__ __forceinline__ void mma16816h(uint32_t* d,
        uint32_t a0, uint32_t a1, uint32_t a2, uint32_t a3,
        uint32_t b0, uint32_t b1) {
    asm volatile("mma.sync.aligned.m16n8k16.row.col.f16.f16.f16.f16 "
                 "{%0,%1}, {%2,%3,%4,%5}, {%6,%7}, {%0,%1};\n"
                 : "+r"(d[0]), "+r"(d[1])
                 : "r"(a0), "r"(a1), "r"(a2), "r"(a3), "r"(b0), "r"(b1));
}

__global__ void __launch_bounds__(NTHREADS, 1)
mlp_kernel(const float* __restrict__ ef, const int* __restrict__ ids,
           const float* __restrict__ W_in, const float* __restrict__ b_in,
           const float* __restrict__ rms_w, const float* __restrict__ W_res,
           const float* __restrict__ b_res, const float* __restrict__ W_out,
           const float* __restrict__ b_out)
{
    extern __shared__ char smem[];
    __half*   Wh   = (__half*)(smem + OFF_W);
    __half*   winh = (__half*)(smem + OFF_WIN16);
    uint32_t* brsh = (uint32_t*)(smem + OFF_BRESH);
    float*    wout = (float*)(smem + OFF_WOUT);

    const int tid = threadIdx.x;

    /* ---- stage weights once per CTA; fold rms_w (per-k) into W_res ---- */
    for (int idx = tid; idx < NRB * HID * HID; idx += NTHREADS) {
        int i   = idx >> 14;
        int rem = idx & 16383;
        int n   = rem >> 7;
        int k   = rem & 127;
        float w = W_res[idx] * rms_w[i * HID + k];
        Wh[(i * HID + n) * WSTRIDE + k] = __float2half(w);
    }
    /* W_in in ldsm layout: row n, k=0..2 weights, k=3 bias, k=4..15 zero */
    for (int idx = tid; idx < HID * 16; idx += NTHREADS) {
        int n = idx >> 4, k = idx & 15;
        float v = (k < 3) ? W_in[n * 3 + k] : (k == 3 ? b_in[n] : 0.f);
        winh[n * WINSTR + k] = __float2half(v);
    }
    for (int idx = tid; idx < HID * (WINSTR - 16); idx += NTHREADS) {
        int n = idx / (WINSTR - 16), k = 16 + idx % (WINSTR - 16);
        winh[n * WINSTR + k] = __float2half(0.f);   /* pad region */
    }
    for (int c = tid; c < HID; c += NTHREADS) wout[c] = W_out[c];
    for (int idx = tid; idx < NRB * 64; idx += NTHREADS) {
        int i = idx >> 6, c2 = idx & 63;
        brsh[idx] = pack_h2(b_res[i * HID + 2 * c2], b_res[i * HID + 2 * c2 + 1]);
    }
    __syncthreads();   /* ONLY block sync — weights read-only afterwards */

    const float bout = b_out[0];
    const int warp = tid >> 5, lane = tid & 31;
    const int q = lane & 3, gid = lane >> 2;

    uint32_t wbase = (uint32_t)__cvta_generic_to_shared(Wh);
    uint32_t laneB = wbase +
        ((((lane & 7) + ((lane >> 4) & 1) * 8) * WSTRIDE) + ((lane >> 3) & 1) * 8) * 2;
    uint32_t wibase = (uint32_t)__cvta_generic_to_shared(winh);
    uint32_t laneWi = wibase +
        ((((lane & 7) + ((lane >> 4) & 1) * 8) * WINSTR) + ((lane >> 3) & 1) * 8) * 2;

    /* prefetch first tile: this thread owns row tile*384 + warp*32 + lane */
    float3 xpre = make_float3(0.f, 0.f, 0.f);
    {
        long r = (long)blockIdx.x * TILE_M + warp * 32 + lane;
        if (r < N_EDGES) xpre = make_float3(ef[r * 3], ef[r * 3 + 1], ef[r * 3 + 2]);
    }

    for (int tile = blockIdx.x; tile < NTILES; tile += gridDim.x) {
        /* ---- distribute x within the warp via shuffles (no smem, no barrier) ----
           rows needed: gid + {0,8,16,24} (s2 in {0,1}, sub {lo,hi}) */
        uint32_t a0[2], a1[2];
        #pragma unroll
        for (int s2 = 0; s2 < 2; s2++) {
            int ra = gid + s2 * 16, rb = ra + 8;
            float ax = __shfl_sync(0xffffffffu, xpre.x, ra);
            float ay = __shfl_sync(0xffffffffu, xpre.y, ra);
            float az = __shfl_sync(0xffffffffu, xpre.z, ra);
            float bx = __shfl_sync(0xffffffffu, xpre.x, rb);
            float by = __shfl_sync(0xffffffffu, xpre.y, rb);
            float bz = __shfl_sync(0xffffffffu, xpre.z, rb);
            a0[s2] = (q == 0) ? pack_h2(ax, ay) : (q == 1) ? pack_h2(az, 1.f) : 0u;
            a1[s2] = (q == 0) ? pack_h2(bx, by) : (q == 1) ? pack_h2(bz, 1.f) : 0u;
        }

        /* prefetch next tile while this one computes */
        {
            int nt = tile + gridDim.x;
            xpre = make_float3(0.f, 0.f, 0.f);
            if (nt < NTILES) {
                long r = (long)nt * TILE_M + warp * 32 + lane;
                if (r < N_EDGES)
                    xpre = make_float3(ef[r * 3], ef[r * 3 + 1], ef[r * 3 + 2]);
            }
        }

        /* ---- residual stream, packed fp16 A-fragment layout ----
           hp[s2][4*ks+0]=(row gid,  cols 16ks+2q,+1)  [4*ks+1]=(row gid+8, same)
           hp[s2][4*ks+2]=(row gid,  cols 16ks+8+2q,+1)[4*ks+3]=(row gid+8, same) */
        uint32_t hp[2][32];
        #pragma unroll
        for (int s2 = 0; s2 < 2; s2++)
            #pragma unroll
            for (int i = 0; i < 32; i++) hp[s2][i] = 0u;

        /* ---- input layer on the tensor pipe ----
           A frag (k=16): k0..2 = x, k3 = 1.0 (bias), k4..15 = 0 */
        #pragma unroll
        for (int jp = 0; jp < 8; jp++) {
            uint32_t b0, b1, b2, b3;
            ldsm_x4(b0, b1, b2, b3, laneWi + (uint32_t)(jp * 16 * WINSTR * 2));
            #pragma unroll
            for (int s2 = 0; s2 < 2; s2++) {
                int j0 = 2 * jp, j1 = 2 * jp + 1;
                int i00 = 4 * (j0 >> 1) + (j0 & 1) * 2;
                int i01 = 4 * (j1 >> 1) + (j1 & 1) * 2;
                mma16816h(&hp[s2][i00], a0[s2], a1[s2], 0u, 0u, b0, b1);
                mma16816h(&hp[s2][i01], a0[s2], a1[s2], 0u, 0u, b2, b3);
            }
        }

        /* sum of squares of h (rows gid = even hp, gid+8 = odd) */
        float ssf[2][2];
        #pragma unroll
        for (int s2 = 0; s2 < 2; s2++) {
            uint32_t n0 = 0u, n1 = 0u;
            #pragma unroll
            for (int i = 0; i < 16; i++) {
                n0 = hfma2_u(hp[s2][2 * i],     hp[s2][2 * i],     n0);
                n1 = hfma2_u(hp[s2][2 * i + 1], hp[s2][2 * i + 1], n1);
            }
            float2 v0 = unpack_h2(n0), v1 = unpack_h2(n1);
            ssf[s2][0] = v0.x + v0.y;
            ssf[s2][1] = v1.x + v1.y;
        }

        /* ---- 4 residual blocks: j-pair-outer so relu overlaps next pair's MMAs ---- */
        #pragma unroll 1
        for (int blk = 0; blk < NRB; blk++) {
            uint32_t sch[2][2];
            #pragma unroll
            for (int s2 = 0; s2 < 2; s2++)
                #pragma unroll
                for (int g = 0; g < 2; g++) {
                    float v = ssf[s2][g];
                    v += __shfl_xor_sync(0xffffffffu, v, 1);
                    v += __shfl_xor_sync(0xffffffffu, v, 2);
                    float s = rsqrtf(v * (1.f / HID) + RMS_EPS);
                    sch[s2][g] = pack_h2(s, s);
                }

            uint32_t y[2][16][2];   /* holds relu(sc*acc + b) after each pair */
            uint32_t lb = laneB + blk * (HID * WSTRIDE * 2);
            const uint32_t* bb2 = brsh + blk * 64;

            #pragma unroll
            for (int jp = 0; jp < 8; jp++) {
                int j0 = 2 * jp, j1 = 2 * jp + 1;
                y[0][j0][0] = y[0][j0][1] = y[0][j1][0] = y[0][j1][1] = 0u;
                y[1][j0][0] = y[1][j0][1] = y[1][j1][0] = y[1][j1][1] = 0u;
                #pragma unroll
                for (int ks = 0; ks < 8; ks++) {
                    uint32_t b0, b1, b2, b3;
                    ldsm_x4(b0, b1, b2, b3,
                            lb + (uint32_t)((jp * 16 * WSTRIDE + ks * 16) * 2));
                    mma16816h(y[0][j0], hp[0][4*ks], hp[0][4*ks+1], hp[0][4*ks+2], hp[0][4*ks+3], b0, b1);
                    mma16816h(y[0][j1], hp[0][4*ks], hp[0][4*ks+1], hp[0][4*ks+2], hp[0][4*ks+3], b2, b3);
                    mma16816h(y[1][j0], hp[1][4*ks], hp[1][4*ks+1], hp[1][4*ks+2], hp[1][4*ks+3], b0, b1);
                    mma16816h(y[1][j1], hp[1][4*ks], hp[1][4*ks+1], hp[1][4*ks+2], hp[1][4*ks+3], b2, b3);
                }
                /* relu(sc*y + b) in place — overlaps next pair's ldsm/mma stream */
                uint32_t bbA = bb2[j0 * 4 + q], bbB = bb2[j1 * 4 + q];
                #pragma unroll
                for (int s2 = 0; s2 < 2; s2++) {
                    y[s2][j0][0] = hmax2z_u(hfma2_u(y[s2][j0][0], sch[s2][0], bbA));
                    y[s2][j0][1] = hmax2z_u(hfma2_u(y[s2][j0][1], sch[s2][1], bbA));
                    y[s2][j1][0] = hmax2z_u(hfma2_u(y[s2][j1][0], sch[s2][0], bbB));
                    y[s2][j1][1] = hmax2z_u(hfma2_u(y[s2][j1][1], sch[s2][1], bbB));
                }
            }

            /* commit residual + next sum-of-squares */
            #pragma unroll
            for (int s2 = 0; s2 < 2; s2++) {
                uint32_t n0 = 0u, n1 = 0u;
                #pragma unroll
                for (int j = 0; j < 16; j++) {
                    int i0 = 4 * (j >> 1) + (j & 1) * 2;
                    hp[s2][i0]     = hadd2_u(hp[s2][i0],     y[s2][j][0]);
                    hp[s2][i0 + 1] = hadd2_u(hp[s2][i0 + 1], y[s2][j][1]);
                    n0 = hfma2_u(hp[s2][i0],     hp[s2][i0],     n0);
                    n1 = hfma2_u(hp[s2][i0 + 1], hp[s2][i0 + 1], n1);
                }
                float2 v0 = unpack_h2(n0), v1 = unpack_h2(n1);
                ssf[s2][0] = v0.x + v0.y;
                ssf[s2][1] = v1.x + v1.y;
            }
        }

        /* ---- output layer (f32) + fused segment-max ---- */
        const float2* w2 = (const float2*)wout;
        #pragma unroll
        for (int s2 = 0; s2 < 2; s2++) {
            float a0v = 0.f, a1v = 0.f;
            #pragma unroll
            for (int j = 0; j < 16; j++) {
                float2 w = w2[j * 4 + q];
                int i0 = 4 * (j >> 1) + (j & 1) * 2;
                float2 hA = unpack_h2(hp[s2][i0]);
                float2 hB = unpack_h2(hp[s2][i0 + 1]);
                a0v += hA.x * w.x + hA.y * w.y;
                a1v += hB.x * w.x + hB.y * w.y;
            }
            a0v += __shfl_xor_sync(0xffffffffu, a0v, 1);
            a0v += __shfl_xor_sync(0xffffffffu, a0v, 2);
            a1v += __shfl_xor_sync(0xffffffffu, a1v, 1);
            a1v += __shfl_xor_sync(0xffffffffu, a1v, 2);
            if (q == 0) {
                long r0 = (long)tile * TILE_M + warp * 32 + s2 * 16 + gid;
                long r1 = r0 + 8;
                float l0 = a0v + bout, l1 = a1v + bout;
                if (r0 < N_EDGES) {
                    g_logits[r0] = l0;
                    atomicMax(&g_segmax[ids[r0]], enc_f(l0));
                }
                if (r1 < N_EDGES) {
                    g_logits[r1] = l1;
                    atomicMax(&g_segmax[ids[r1]], enc_f(l1));
                }
            }
        }
    }
}

__global__ void init_kernel() {
    int i = blockIdx.x * blockDim.x + threadIdx.x;
    if (i < NUM_SEGS) { g_segmax[i] = 0u; g_segsum[i] = 0.f; }
}

__global__ void exp_kernel(const int* __restrict__ ids, float* __restrict__ out) {
    int i = blockIdx.x * blockDim.x + threadIdx.x;
    if (i < N_EDGES) {
        int s = ids[i];
        float m = dec_f(g_segmax[s]);
        float e = expf(g_logits[i] - m);
        out[i] = e;
        atomicAdd(&g_segsum[s], e);
    }
}

__global__ void norm_kernel(const int* __restrict__ ids, float* __restrict__ out) {
    int i = blockIdx.x * blockDim.x + threadIdx.x;
    if (i < N_EDGES) out[i] = out[i] / g_segsum[ids[i]];
}

extern "C" void kernel_launch(void* const* d_in, const int* in_sizes, int n_in,
                              void* d_out, int out_size)
{
    const float* ef    = (const float*)d_in[0];
    const int*   ids   = (const int*)d_in[1];
    const float* W_in  = (const float*)d_in[2];
    const float* b_in  = (const float*)d_in[3];
    const float* rms_w = (const float*)d_in[4];
    const float* W_res = (const float*)d_in[5];
    const float* b_res = (const float*)d_in[6];
    const float* W_out = (const float*)d_in[7];
    const float* b_out = (const float*)d_in[8];
    float* out = (float*)d_out;

    cudaFuncSetAttribute(mlp_kernel, cudaFuncAttributeMaxDynamicSharedMemorySize, SMEM_BYTES);

    int dev = 0, sms = 148;
    cudaGetDevice(&dev);
    cudaDeviceGetAttribute(&sms, cudaDevAttrMultiProcessorCount, dev);
    if (sms <= 0) sms = 148;

    init_kernel<<<(NUM_SEGS + 255) / 256, 256>>>();
    mlp_kernel<<<sms, NTHREADS, SMEM_BYTES>>>(ef, ids, W_in, b_in, rms_w,
                                              W_res, b_res, W_out, b_out);
    exp_kernel<<<(N_EDGES + 255) / 256, 256>>>(ids, out);
    norm_kernel<<<(N_EDGES + 255) / 256, 256>>>(ids, out);
}

// round 13
// speedup vs baseline: 1.9125x; 1.0350x over previous
#include <cuda_runtime.h>
#include <cuda_fp16.h>
#include <cstdint>

#define N_EDGES  2000000
#define NUM_SEGS 500000
#define HID      128
#define NRB      4
#define TILE_M   384
#define NTILES   ((N_EDGES + TILE_M - 1) / TILE_M)   /* 5209, last tile 128 rows */
#define NTHREADS 384
#define WSTRIDE  136                  /* halves per W row: 128 + 8 pad */
#define WINSTR   24                   /* halves per W_in row: 16 + 8 pad */
#define OWSTR    136                  /* halves per w_out ldsm row */
#define RMS_EPS  1.1920928955078125e-07f

/* SMEM layout (bytes) */
#define OFF_W     0
#define SZ_W      (NRB * HID * WSTRIDE * 2)          /* 139264 */
#define OFF_WIN16 (OFF_W + SZ_W)                     /* half[128*24] ldsm layout */
#define OFF_BRESH (OFF_WIN16 + HID * WINSTR * 2)     /* half2[4*64]  */
#define OFF_WOH   (OFF_BRESH + NRB * 64 * 4)         /* half[8*136] w_out ldsm B-layout */
#define SMEM_BYTES (OFF_WOH + 8 * OWSTR * 2)

__device__ float    g_logits[N_EDGES];
__device__ unsigned g_segmax[NUM_SEGS];
__device__ float    g_segsum[NUM_SEGS];

__device__ __forceinline__ unsigned enc_f(float f) {
    unsigned b = __float_as_uint(f);
    return (b & 0x80000000u) ? ~b : (b | 0x80000000u);
}
__device__ __forceinline__ float dec_f(unsigned k) {
    unsigned b = (k & 0x80000000u) ? (k & 0x7FFFFFFFu) : ~k;
    return __uint_as_float(b);
}
__device__ __forceinline__ uint32_t pack_h2(float lo, float hi) {
    __half2 h = __floats2half2_rn(lo, hi);
    return *reinterpret_cast<uint32_t*>(&h);
}
__device__ __forceinline__ float2 unpack_h2(uint32_t u) {
    return __half22float2(*reinterpret_cast<__half2*>(&u));
}
__device__ __forceinline__ uint32_t hadd2_u(uint32_t a, uint32_t b) {
    __half2 r = __hadd2(*reinterpret_cast<__half2*>(&a), *reinterpret_cast<__half2*>(&b));
    return *reinterpret_cast<uint32_t*>(&r);
}
__device__ __forceinline__ uint32_t hmax2z_u(uint32_t a) {
    __half2 z = __float2half2_rn(0.f);
    __half2 r = __hmax2(*reinterpret_cast<__half2*>(&a), z);
    return *reinterpret_cast<uint32_t*>(&r);
}
__device__ __forceinline__ uint32_t hfma2_u(uint32_t a, uint32_t b, uint32_t c) {
    __half2 r = __hfma2(*reinterpret_cast<__half2*>(&a),
                        *reinterpret_cast<__half2*>(&b),
                        *reinterpret_cast<__half2*>(&c));
    return *reinterpret_cast<uint32_t*>(&r);
}
__device__ __forceinline__ void ldsm_x4(uint32_t& r0, uint32_t& r1, uint32_t& r2, uint32_t& r3,
                                        uint32_t addr) {
    asm volatile("ldmatrix.sync.aligned.m8n8.x4.shared.b16 {%0,%1,%2,%3}, [%4];\n"
                 : "=r"(r0), "=r"(r1), "=r"(r2), "=r"(r3) : "r"(addr));
}
__device__ __forceinline__ void ldsm_x2(uint32_t& r0, uint32_t& r1, uint32_t addr) {
    asm volatile("ldmatrix.sync.aligned.m8n8.x2.shared.b16 {%0,%1}, [%2];\n"
                 : "=r"(r0), "=r"(r1) : "r"(addr));
}
/* f16 accumulator variant: d = {d0,d1} half2 regs. */
__device__ __forceinline__ void mma16816h(uint32_t* d,
        uint32_t a0, uint32_t a1, uint32_t a2, uint32_t a3,
        uint32_t b0, uint32_t b1) {
    asm volatile("mma.sync.aligned.m16n8k16.row.col.f16.f16.f16.f16 "
                 "{%0,%1}, {%2,%3,%4,%5}, {%6,%7}, {%0,%1};\n"
                 : "+r"(d[0]), "+r"(d[1])
                 : "r"(a0), "r"(a1), "r"(a2), "r"(a3), "r"(b0), "r"(b1));
}
/* f32 accumulator variant (output layer): d0=(gid,c2q) d1=(gid,c2q+1) d2=(gid+8,c2q) d3=... */
__device__ __forceinline__ void mma16816f(float* d,
        uint32_t a0, uint32_t a1, uint32_t a2, uint32_t a3,
        uint32_t b0, uint32_t b1) {
    asm volatile("mma.sync.aligned.m16n8k16.row.col.f32.f16.f16.f32 "
                 "{%0,%1,%2,%3}, {%4,%5,%6,%7}, {%8,%9}, {%0,%1,%2,%3};\n"
                 : "+f"(d[0]), "+f"(d[1]), "+f"(d[2]), "+f"(d[3])
                 : "r"(a0), "r"(a1), "r"(a2), "r"(a3), "r"(b0), "r"(b1));
}

__global__ void __launch_bounds__(NTHREADS, 1)
mlp_kernel(const float* __restrict__ ef, const int* __restrict__ ids,
           const float* __restrict__ W_in, const float* __restrict__ b_in,
           const float* __restrict__ rms_w, const float* __restrict__ W_res,
           const float* __restrict__ b_res, const float* __restrict__ W_out,
           const float* __restrict__ b_out)
{
    extern __shared__ char smem[];
    __half*   Wh   = (__half*)(smem + OFF_W);
    __half*   winh = (__half*)(smem + OFF_WIN16);
    uint32_t* brsh = (uint32_t*)(smem + OFF_BRESH);
    __half*   woh  = (__half*)(smem + OFF_WOH);

    const int tid = threadIdx.x;

    /* ---- stage weights once per CTA; fold rms_w (per-k) into W_res ---- */
    for (int idx = tid; idx < NRB * HID * HID; idx += NTHREADS) {
        int i   = idx >> 14;
        int rem = idx & 16383;
        int n   = rem >> 7;
        int k   = rem & 127;
        float w = W_res[idx] * rms_w[i * HID + k];
        Wh[(i * HID + n) * WSTRIDE + k] = __float2half(w);
    }
    /* W_in in ldsm layout: row n, k=0..2 weights, k=3 bias, k=4..15 zero */
    for (int idx = tid; idx < HID * 16; idx += NTHREADS) {
        int n = idx >> 4, k = idx & 15;
        float v = (k < 3) ? W_in[n * 3 + k] : (k == 3 ? b_in[n] : 0.f);
        winh[n * WINSTR + k] = __float2half(v);
    }
    for (int idx = tid; idx < HID * (WINSTR - 16); idx += NTHREADS) {
        int n = idx / (WINSTR - 16), k = 16 + idx % (WINSTR - 16);
        winh[n * WINSTR + k] = __float2half(0.f);
    }
    /* w_out in ldsm B-layout: row 0 = w_out, rows 1-7 zero */
    for (int idx = tid; idx < 8 * OWSTR; idx += NTHREADS) {
        int n = idx / OWSTR, k = idx % OWSTR;
        woh[idx] = __float2half((n == 0 && k < HID) ? W_out[k] : 0.f);
    }
    for (int idx = tid; idx < NRB * 64; idx += NTHREADS) {
        int i = idx >> 6, c2 = idx & 63;
        brsh[idx] = pack_h2(b_res[i * HID + 2 * c2], b_res[i * HID + 2 * c2 + 1]);
    }
    __syncthreads();   /* ONLY block sync — weights read-only afterwards */

    const float bout = b_out[0];
    const int warp = tid >> 5, lane = tid & 31;
    const int q = lane & 3, gid = lane >> 2;

    uint32_t wbase = (uint32_t)__cvta_generic_to_shared(Wh);
    uint32_t laneB = wbase +
        ((((lane & 7) + ((lane >> 4) & 1) * 8) * WSTRIDE) + ((lane >> 3) & 1) * 8) * 2;
    uint32_t wibase = (uint32_t)__cvta_generic_to_shared(winh);
    uint32_t laneWi = wibase +
        ((((lane & 7) + ((lane >> 4) & 1) * 8) * WINSTR) + ((lane >> 3) & 1) * 8) * 2;
    uint32_t wobase = (uint32_t)__cvta_generic_to_shared(woh);
    uint32_t laneO = wobase + (((lane & 7) * OWSTR) + ((lane >> 3) & 1) * 8) * 2;

    /* prefetch first tile: this thread owns row tile*384 + warp*32 + lane */
    float3 xpre = make_float3(0.f, 0.f, 0.f);
    int ipre = 0;
    {
        long r = (long)blockIdx.x * TILE_M + warp * 32 + lane;
        if (r < N_EDGES) {
            xpre = make_float3(ef[r * 3], ef[r * 3 + 1], ef[r * 3 + 2]);
            ipre = ids[r];
        }
    }

    for (int tile = blockIdx.x; tile < NTILES; tile += gridDim.x) {
        /* ---- distribute x within the warp via shuffles ---- */
        uint32_t a0[2], a1[2];
        #pragma unroll
        for (int s2 = 0; s2 < 2; s2++) {
            int ra = gid + s2 * 16, rb = ra + 8;
            float ax = __shfl_sync(0xffffffffu, xpre.x, ra);
            float ay = __shfl_sync(0xffffffffu, xpre.y, ra);
            float az = __shfl_sync(0xffffffffu, xpre.z, ra);
            float bx = __shfl_sync(0xffffffffu, xpre.x, rb);
            float by = __shfl_sync(0xffffffffu, xpre.y, rb);
            float bz = __shfl_sync(0xffffffffu, xpre.z, rb);
            a0[s2] = (q == 0) ? pack_h2(ax, ay) : (q == 1) ? pack_h2(az, 1.f) : 0u;
            a1[s2] = (q == 0) ? pack_h2(bx, by) : (q == 1) ? pack_h2(bz, 1.f) : 0u;
        }
        const int icur = ipre;

        /* prefetch next tile while this one computes */
        {
            int nt = tile + gridDim.x;
            xpre = make_float3(0.f, 0.f, 0.f);
            if (nt < NTILES) {
                long r = (long)nt * TILE_M + warp * 32 + lane;
                if (r < N_EDGES) {
                    xpre = make_float3(ef[r * 3], ef[r * 3 + 1], ef[r * 3 + 2]);
                    ipre = ids[r];
                }
            }
        }

        /* ---- residual stream, packed fp16 A-fragment layout ---- */
        uint32_t hp[2][32];
        #pragma unroll
        for (int s2 = 0; s2 < 2; s2++)
            #pragma unroll
            for (int i = 0; i < 32; i++) hp[s2][i] = 0u;

        /* ---- input layer on the tensor pipe ---- */
        #pragma unroll
        for (int jp = 0; jp < 8; jp++) {
            uint32_t b0, b1, b2, b3;
            ldsm_x4(b0, b1, b2, b3, laneWi + (uint32_t)(jp * 16 * WINSTR * 2));
            #pragma unroll
            for (int s2 = 0; s2 < 2; s2++) {
                int j0 = 2 * jp, j1 = 2 * jp + 1;
                int i00 = 4 * (j0 >> 1) + (j0 & 1) * 2;
                int i01 = 4 * (j1 >> 1) + (j1 & 1) * 2;
                mma16816h(&hp[s2][i00], a0[s2], a1[s2], 0u, 0u, b0, b1);
                mma16816h(&hp[s2][i01], a0[s2], a1[s2], 0u, 0u, b2, b3);
            }
        }

        /* sum of squares of h */
        float ssf[2][2];
        #pragma unroll
        for (int s2 = 0; s2 < 2; s2++) {
            uint32_t n0 = 0u, n1 = 0u;
            #pragma unroll
            for (int i = 0; i < 16; i++) {
                n0 = hfma2_u(hp[s2][2 * i],     hp[s2][2 * i],     n0);
                n1 = hfma2_u(hp[s2][2 * i + 1], hp[s2][2 * i + 1], n1);
            }
            float2 v0 = unpack_h2(n0), v1 = unpack_h2(n1);
            ssf[s2][0] = v0.x + v0.y;
            ssf[s2][1] = v1.x + v1.y;
        }

        /* ---- 4 residual blocks: j-pair-outer, relu overlapped ---- */
        #pragma unroll 1
        for (int blk = 0; blk < NRB; blk++) {
            uint32_t sch[2][2];
            #pragma unroll
            for (int s2 = 0; s2 < 2; s2++)
                #pragma unroll
                for (int g = 0; g < 2; g++) {
                    float v = ssf[s2][g];
                    v += __shfl_xor_sync(0xffffffffu, v, 1);
                    v += __shfl_xor_sync(0xffffffffu, v, 2);
                    float s = rsqrtf(v * (1.f / HID) + RMS_EPS);
                    sch[s2][g] = pack_h2(s, s);
                }

            uint32_t y[2][16][2];
            uint32_t lb = laneB + blk * (HID * WSTRIDE * 2);
            const uint32_t* bb2 = brsh + blk * 64;

            #pragma unroll
            for (int jp = 0; jp < 8; jp++) {
                int j0 = 2 * jp, j1 = 2 * jp + 1;
                y[0][j0][0] = y[0][j0][1] = y[0][j1][0] = y[0][j1][1] = 0u;
                y[1][j0][0] = y[1][j0][1] = y[1][j1][0] = y[1][j1][1] = 0u;
                #pragma unroll
                for (int ks = 0; ks < 8; ks++) {
                    uint32_t b0, b1, b2, b3;
                    ldsm_x4(b0, b1, b2, b3,
                            lb + (uint32_t)((jp * 16 * WSTRIDE + ks * 16) * 2));
                    mma16816h(y[0][j0], hp[0][4*ks], hp[0][4*ks+1], hp[0][4*ks+2], hp[0][4*ks+3], b0, b1);
                    mma16816h(y[0][j1], hp[0][4*ks], hp[0][4*ks+1], hp[0][4*ks+2], hp[0][4*ks+3], b2, b3);
                    mma16816h(y[1][j0], hp[1][4*ks], hp[1][4*ks+1], hp[1][4*ks+2], hp[1][4*ks+3], b0, b1);
                    mma16816h(y[1][j1], hp[1][4*ks], hp[1][4*ks+1], hp[1][4*ks+2], hp[1][4*ks+3], b2, b3);
                }
                uint32_t bbA = bb2[j0 * 4 + q], bbB = bb2[j1 * 4 + q];
                #pragma unroll
                for (int s2 = 0; s2 < 2; s2++) {
                    y[s2][j0][0] = hmax2z_u(hfma2_u(y[s2][j0][0], sch[s2][0], bbA));
                    y[s2][j0][1] = hmax2z_u(hfma2_u(y[s2][j0][1], sch[s2][1], bbA));
                    y[s2][j1][0] = hmax2z_u(hfma2_u(y[s2][j1][0], sch[s2][0], bbB));
                    y[s2][j1][1] = hmax2z_u(hfma2_u(y[s2][j1][1], sch[s2][1], bbB));
                }
            }

            /* commit residual + next sum-of-squares */
            #pragma unroll
            for (int s2 = 0; s2 < 2; s2++) {
                uint32_t n0 = 0u, n1 = 0u;
                #pragma unroll
                for (int j = 0; j < 16; j++) {
                    int i0 = 4 * (j >> 1) + (j & 1) * 2;
                    hp[s2][i0]     = hadd2_u(hp[s2][i0],     y[s2][j][0]);
                    hp[s2][i0 + 1] = hadd2_u(hp[s2][i0 + 1], y[s2][j][1]);
                    n0 = hfma2_u(hp[s2][i0],     hp[s2][i0],     n0);
                    n1 = hfma2_u(hp[s2][i0 + 1], hp[s2][i0 + 1], n1);
                }
                float2 v0 = unpack_h2(n0), v1 = unpack_h2(n1);
                ssf[s2][0] = v0.x + v0.y;
                ssf[s2][1] = v1.x + v1.y;
            }
        }

        /* ---- output layer on the tensor pipe (f32 accum, n=8 tile, col0 live) ---- */
        float d[2][4];
        d[0][0] = d[0][1] = d[0][2] = d[0][3] = 0.f;
        d[1][0] = d[1][1] = d[1][2] = d[1][3] = 0.f;
        #pragma unroll
        for (int ks = 0; ks < 8; ks++) {
            uint32_t b0, b1;
            ldsm_x2(b0, b1, laneO + (uint32_t)(ks * 32));
            mma16816f(d[0], hp[0][4*ks], hp[0][4*ks+1], hp[0][4*ks+2], hp[0][4*ks+3], b0, b1);
            mma16816f(d[1], hp[1][4*ks], hp[1][4*ks+1], hp[1][4*ks+2], hp[1][4*ks+3], b0, b1);
        }
        /* ids for this warp's rows, via shuffle of prefetched icur */
        int idA[2], idB[2];
        #pragma unroll
        for (int s2 = 0; s2 < 2; s2++) {
            idA[s2] = __shfl_sync(0xffffffffu, icur, s2 * 16 + gid);
            idB[s2] = __shfl_sync(0xffffffffu, icur, s2 * 16 + gid + 8);
        }
        if (q == 0) {
            #pragma unroll
            for (int s2 = 0; s2 < 2; s2++) {
                long r0 = (long)tile * TILE_M + warp * 32 + s2 * 16 + gid;
                long r1 = r0 + 8;
                float l0 = d[s2][0] + bout, l1 = d[s2][2] + bout;
                if (r0 < N_EDGES) {
                    g_logits[r0] = l0;
                    atomicMax(&g_segmax[idA[s2]], enc_f(l0));
                }
                if (r1 < N_EDGES) {
                    g_logits[r1] = l1;
                    atomicMax(&g_segmax[idB[s2]], enc_f(l1));
                }
            }
        }
    }
}

__global__ void init_kernel() {
    int i = blockIdx.x * blockDim.x + threadIdx.x;
    if (i < NUM_SEGS) { g_segmax[i] = 0u; g_segsum[i] = 0.f; }
}

__global__ void exp_kernel(const int* __restrict__ ids, float* __restrict__ out) {
    int i = blockIdx.x * blockDim.x + threadIdx.x;
    int lane = threadIdx.x & 31;
    int s = -1;
    float e = 0.f;
    if (i < N_EDGES) {
        s = ids[i];
        float m = dec_f(g_segmax[s]);
        e = expf(g_logits[i] - m);
        out[i] = e;
    }
    /* warp-aggregated segment sum (ids sorted -> groups are contiguous lanes) */
    unsigned grp = __match_any_sync(0xffffffffu, s);
    int lo = __ffs(grp) - 1;
    int hi = 31 - __clz(grp);
    float v = e;
    #pragma unroll
    for (int off = 16; off; off >>= 1) {
        float t = __shfl_down_sync(0xffffffffu, v, off);
        if (lane + off <= hi) v += t;
    }
    if (lane == lo && s >= 0) atomicAdd(&g_segsum[s], v);
}

__global__ void norm_kernel(const int* __restrict__ ids, float* __restrict__ out) {
    int i = blockIdx.x * blockDim.x + threadIdx.x;
    if (i < N_EDGES) out[i] = out[i] / g_segsum[ids[i]];
}

extern "C" void kernel_launch(void* const* d_in, const int* in_sizes, int n_in,
                              void* d_out, int out_size)
{
    const float* ef    = (const float*)d_in[0];
    const int*   ids   = (const int*)d_in[1];
    const float* W_in  = (const float*)d_in[2];
    const float* b_in  = (const float*)d_in[3];
    const float* rms_w = (const float*)d_in[4];
    const float* W_res = (const float*)d_in[5];
    const float* b_res = (const float*)d_in[6];
    const float* W_out = (const float*)d_in[7];
    const float* b_out = (const float*)d_in[8];
    float* out = (float*)d_out;

    cudaFuncSetAttribute(mlp_kernel, cudaFuncAttributeMaxDynamicSharedMemorySize, SMEM_BYTES);

    int dev = 0, sms = 148;
    cudaGetDevice(&dev);
    cudaDeviceGetAttribute(&sms, cudaDevAttrMultiProcessorCount, dev);
    if (sms <= 0) sms = 148;

    init_kernel<<<(NUM_SEGS + 255) / 256, 256>>>();
    mlp_kernel<<<sms, NTHREADS, SMEM_BYTES>>>(ef, ids, W_in, b_in, rms_w,
                                              W_res, b_res, W_out, b_out);
    exp_kernel<<<(N_EDGES + 255) / 256, 256>>>(ids, out);
    norm_kernel<<<(N_EDGES + 255) / 256, 256>>>(ids, out);
}